// round 7
// baseline (speedup 1.0000x reference)
#include <cuda_runtime.h>
#include <cstdint>

#define B_   8
#define C_   256
#define CQ_  32
#define H_   128
#define W_   128
#define HW_  (H_*W_)

typedef unsigned long long u64;

// ---------------- scratch ----------------------------------------------------
__device__ float g_qc [(size_t)B_*HW_*CQ_];   // [b, p(=h*W+w), c]
__device__ float g_kc [(size_t)B_*HW_*CQ_];   // [b, p, c]
__device__ float g_v  [(size_t)B_*C_*HW_];    // [b, c, h, w]
__device__ float g_vt [(size_t)B_*C_*HW_];    // [b, c, w, h]
__device__ float g_att[(size_t)B_*H_*W_*256]; // [b,h,w, 0:128=H-half, 128:256=W-half]
__device__ float g_oht[(size_t)B_*C_*HW_];    // outH transposed: [b,c,w,h]
__device__ float g_ow [(size_t)B_*C_*HW_];    // outW: [b,c,h,w]

#define NEGF (__int_as_float(0xff800000))

// ---------------- packed fp32x2 helpers --------------------------------------
__device__ __forceinline__ void fma2(u64& d, u64 a, u64 b) {
    asm("fma.rn.f32x2 %0, %1, %2, %0;" : "+l"(d) : "l"(a), "l"(b));
}
__device__ __forceinline__ float hadd2(u64 v) {
    float lo, hi;
    asm("mov.b64 {%0,%1}, %2;" : "=f"(lo), "=f"(hi) : "l"(v));
    return lo + hi;
}
__device__ __forceinline__ void st2x(float* p, float4 v) {   // 2x 8B stores
    *(float2*)p       = make_float2(v.x, v.y);
    *(float2*)(p + 2) = make_float2(v.z, v.w);
}

// ---------------- exact 64th-largest, 4 rows, packed counts + early exit -----
__device__ __forceinline__ void topk64x4(const float v[4][4], float thr[4])
{
    unsigned keys[4][4];
    #pragma unroll
    for (int r = 0; r < 4; ++r)
        #pragma unroll
        for (int j = 0; j < 4; ++j) {
            unsigned u = __float_as_uint(v[r][j]);
            keys[r][j] = (u & 0x80000000u) ? ~u : (u | 0x80000000u);
        }
    unsigned prefix[4] = {0, 0, 0, 0};
    unsigned need[4]   = {64, 64, 64, 64};
    unsigned cand[4]   = {128, 128, 128, 128};
    int      ebit[4]   = {0, 0, 0, 0};
    unsigned done = 0;

    for (int bit = 31; bit >= 0; --bit) {
        unsigned packed = 0;
        #pragma unroll
        for (int r = 0; r < 4; ++r) {
            if (!(done & (1u << r))) {            // warp-uniform branch
                unsigned want = (prefix[r] >> bit) | 1u;
                unsigned c = 0;
                #pragma unroll
                for (int j = 0; j < 4; ++j)
                    c += (unsigned)((keys[r][j] >> bit) == want);
                packed += c << (8 * r);
            }
        }
        packed = __reduce_add_sync(0xffffffffu, packed);
        #pragma unroll
        for (int r = 0; r < 4; ++r) {
            if (!(done & (1u << r))) {
                unsigned c = (packed >> (8 * r)) & 255u;
                if (c >= need[r]) { prefix[r] |= 1u << bit; cand[r] = c; }
                else              { need[r] -= c; cand[r] -= c; }
                if (cand[r] == need[r]) { done |= 1u << r; ebit[r] = bit; }
            }
        }
        if (done == 15u) break;
    }
    #pragma unroll
    for (int r = 0; r < 4; ++r) {
        unsigned key;
        if (done & (1u << r)) {                   // warp-uniform
            unsigned mn = 0xFFFFFFFFu;
            #pragma unroll
            for (int j = 0; j < 4; ++j) {
                bool match = (((keys[r][j] ^ prefix[r]) >> ebit[r]) == 0);
                unsigned cand_k = match ? keys[r][j] : 0xFFFFFFFFu;
                mn = cand_k < mn ? cand_k : mn;
            }
            key = __reduce_min_sync(0xffffffffu, mn);
        } else {
            key = prefix[r];                      // exact full-width prefix
        }
        unsigned u = (key & 0x80000000u) ? (key ^ 0x80000000u) : ~key;
        thr[r] = __uint_as_float(u);
    }
}

// ---------------- small projection body (q/k): 32o x 128p, 4x4 tile ----------
__device__ __forceinline__ void proj_qk_body(
    const float* __restrict__ X, const float* __restrict__ Wm,
    const float* __restrict__ bias, float* __restrict__ Y,
    int b, int p0, float* sm)
{
    float* Ws = sm;            // [32][34]
    float* Xs = sm + 32 * 34;  // [128 phys(p)][34]
    const int t  = threadIdx.x;
    const int tx = t & 31, ty = t >> 5;
    const float* Xb = X + (size_t)b * C_ * HW_ + p0;

    u64 acc[4][4] = {};
    for (int kc = 0; kc < C_; kc += 32) {
        #pragma unroll
        for (int i = 0; i < 4; ++i) {
            int idx = t + i * 256;
            int o = idx >> 5, c = idx & 31;
            Ws[o * 34 + c] = Wm[o * C_ + kc + c];
        }
        #pragma unroll
        for (int i = 0; i < 4; ++i) {            // Xs transposed fill, row-perm
            int idx = t + i * 256;
            int c = idx >> 5, p4 = idx & 31;
            float4 xv = *(const float4*)(Xb + (size_t)(kc + c) * HW_ + p4 * 4);
            Xs[(0 * 32 + p4) * 34 + c] = xv.x;
            Xs[(1 * 32 + p4) * 34 + c] = xv.y;
            Xs[(2 * 32 + p4) * 34 + c] = xv.z;
            Xs[(3 * 32 + p4) * 34 + c] = xv.w;
        }
        __syncthreads();
        #pragma unroll
        for (int cp = 0; cp < 16; ++cp) {
            u64 a2[4], b2[4];
            #pragma unroll
            for (int i = 0; i < 4; ++i)
                a2[i] = *(const u64*)&Ws[(ty * 4 + i) * 34 + 2 * cp];
            #pragma unroll
            for (int j = 0; j < 4; ++j)          // col p = tx*4+j -> phys j*32+tx
                b2[j] = *(const u64*)&Xs[(j * 32 + tx) * 34 + 2 * cp];
            #pragma unroll
            for (int i = 0; i < 4; ++i)
                #pragma unroll
                for (int j = 0; j < 4; ++j)
                    fma2(acc[i][j], a2[i], b2[j]);
        }
        __syncthreads();
    }
    #pragma unroll
    for (int j = 0; j < 4; ++j) {
        float4 r;
        r.x = hadd2(acc[0][j]) + bias[ty * 4 + 0];
        r.y = hadd2(acc[1][j]) + bias[ty * 4 + 1];
        r.z = hadd2(acc[2][j]) + bias[ty * 4 + 2];
        r.w = hadd2(acc[3][j]) + bias[ty * 4 + 3];
        *(float4*)(Y + ((size_t)b * HW_ + p0 + tx * 4 + j) * CQ_ + ty * 4) = r;
    }
}

// ---------------- v projection body: 128o x 128p, 8x8 tile -------------------
__device__ __forceinline__ void proj_v_body(
    const float* __restrict__ X, const float* __restrict__ Wm,
    const float* __restrict__ bias, float* __restrict__ Y,
    int b, int o0, int p0, float* sm)
{
    float* Ws = sm;             // [128 o][34]
    float* Xs = sm + 128 * 34;  // [128 p][34]
    const int t  = threadIdx.x;
    const int tx = t & 15, ty = t >> 4;
    const float* Xb = X + (size_t)b * C_ * HW_ + p0;

    u64 acc[8][8] = {};
    for (int kc = 0; kc < C_; kc += 32) {
        #pragma unroll
        for (int i = 0; i < 4; ++i) {            // Ws: straight copy
            int idx = t + i * 256;
            int o = idx >> 3, c4 = (idx & 7) * 4;
            st2x(&Ws[o * 34 + c4], *(const float4*)(Wm + (size_t)(o0 + o) * C_ + kc + c4));
        }
        #pragma unroll
        for (int i = 0; i < 4; ++i) {            // Xs: transposed fill
            int idx = t + i * 256;
            int c = idx >> 5, p4 = idx & 31;
            float4 xv = *(const float4*)(Xb + (size_t)(kc + c) * HW_ + p4 * 4);
            Xs[(p4 * 4 + 0) * 34 + c] = xv.x;
            Xs[(p4 * 4 + 1) * 34 + c] = xv.y;
            Xs[(p4 * 4 + 2) * 34 + c] = xv.z;
            Xs[(p4 * 4 + 3) * 34 + c] = xv.w;
        }
        __syncthreads();
        #pragma unroll
        for (int cp = 0; cp < 16; ++cp) {
            u64 a2[8], b2[8];
            #pragma unroll
            for (int i = 0; i < 8; ++i) a2[i] = *(const u64*)&Ws[(ty + 16 * i) * 34 + 2 * cp];
            #pragma unroll
            for (int j = 0; j < 8; ++j) b2[j] = *(const u64*)&Xs[(tx + 16 * j) * 34 + 2 * cp];
            #pragma unroll
            for (int i = 0; i < 8; ++i)
                #pragma unroll
                for (int j = 0; j < 8; ++j)
                    fma2(acc[i][j], a2[i], b2[j]);
        }
        __syncthreads();
    }
    #pragma unroll
    for (int i = 0; i < 8; ++i) {
        int o = o0 + ty + 16 * i;
        float bv = bias[o];
        float* dst = Y + ((size_t)b * C_ + o) * HW_ + p0;
        #pragma unroll
        for (int j = 0; j < 8; ++j)
            dst[tx + 16 * j] = hadd2(acc[i][j]) + bv;
    }
}

// ---------------- K1: all projections fused (256 threads) --------------------
// blocks [0,2048): projv(8x8), [2048,3072): projq, [3072,4096): projk
__global__ void __launch_bounds__(256, 2) k1_proj(
    const float* __restrict__ x1, const float* __restrict__ x2,
    const float* __restrict__ Wq, const float* __restrict__ bq,
    const float* __restrict__ Wk, const float* __restrict__ bk,
    const float* __restrict__ Wv, const float* __restrict__ bv)
{
    extern __shared__ __align__(16) float sm[];
    const int id = blockIdx.x;
    if (id < 2048) {
        int b = id >> 8, oblk = (id >> 7) & 1, pblk = id & 127;
        proj_v_body(x2, Wv, bv, g_v, b, oblk * 128, pblk * 128, sm);
    } else if (id < 3072) {
        int r = id - 2048;
        proj_qk_body(x1, Wq, bq, g_qc, r >> 7, (r & 127) * 128, sm);
    } else {
        int r = id - 3072;
        proj_qk_body(x2, Wk, bk, g_kc, r >> 7, (r & 127) * 128, sm);
    }
}

// ---------------- eH body (512 threads) ---------------------------------------
__device__ __forceinline__ void eH_body(int w, int b, float* sm)
{
    float* Qs = sm;               // [h 128][34]
    float* Ks = sm + 128 * 34;    // [g 128][34]
    float* Es = sm + 2 * 128 * 34;// [128][132]
    const int t = threadIdx.x;
    {
        const float* qb = g_qc + ((size_t)b * HW_ + w) * CQ_;
        const float* kb = g_kc + ((size_t)b * HW_ + w) * CQ_;
        #pragma unroll
        for (int i = 0; i < 2; ++i) {
            int idx = t + i * 512;            // 1024 float4s
            int h = idx >> 3, c4 = (idx & 7) * 4;
            size_t off = (size_t)h * W_ * CQ_ + c4;
            st2x(&Qs[h * 34 + c4], *(const float4*)(qb + off));
            st2x(&Ks[h * 34 + c4], *(const float4*)(kb + off));
        }
    }
    __syncthreads();
    const int tx = t & 15, ty = t >> 4;
    u64 acc[4][8] = {};
    #pragma unroll 4
    for (int cp = 0; cp < 16; ++cp) {
        u64 a2[4], b2[8];
        #pragma unroll
        for (int i = 0; i < 4; ++i) a2[i] = *(const u64*)&Qs[(ty + 32 * i) * 34 + 2 * cp];
        #pragma unroll
        for (int j = 0; j < 8; ++j) b2[j] = *(const u64*)&Ks[(tx + 16 * j) * 34 + 2 * cp];
        #pragma unroll
        for (int i = 0; i < 4; ++i)
            #pragma unroll
            for (int j = 0; j < 8; ++j)
                fma2(acc[i][j], a2[i], b2[j]);
    }
    #pragma unroll
    for (int i = 0; i < 4; ++i) {
        int h = ty + 32 * i;
        #pragma unroll
        for (int j = 0; j < 8; ++j) {
            int g = tx + 16 * j;
            Es[h * 132 + g] = (h == g) ? NEGF : hadd2(acc[i][j]);
        }
    }
    __syncthreads();
    const int lane = t & 31, wid = t >> 5;  // 16 warps, 8 rows each
    #pragma unroll
    for (int grp = 0; grp < 2; ++grp) {
        float v[4][4];
        int rr[4];
        #pragma unroll
        for (int s = 0; s < 4; ++s) {
            rr[s] = wid + 16 * (grp * 4 + s);
            float4 x = *(const float4*)&Es[rr[s] * 132 + lane * 4];
            v[s][0] = x.x; v[s][1] = x.y; v[s][2] = x.z; v[s][3] = x.w;
        }
        float thr[4];
        topk64x4(v, thr);
        #pragma unroll
        for (int s = 0; s < 4; ++s) {
            float4 o;
            o.x = v[s][0] >= thr[s] ? v[s][0] : NEGF;
            o.y = v[s][1] >= thr[s] ? v[s][1] : NEGF;
            o.z = v[s][2] >= thr[s] ? v[s][2] : NEGF;
            o.w = v[s][3] >= thr[s] ? v[s][3] : NEGF;
            *(float4*)(g_att + (((size_t)b * H_ + rr[s]) * W_ + w) * 256 + lane * 4) = o;
        }
    }
}

// ---------------- transpose body: 64x64 tile, 512 threads --------------------
__device__ __forceinline__ void transpose_body(int n, int w0, int h0, float* sm)
{
    float* tile = sm;                       // [64][65]
    const float* s = g_v  + (size_t)n * HW_;
    float*       d = g_vt + (size_t)n * HW_;
    const int t = threadIdx.x;
    const int col = t & 63, rg = t >> 6;    // rg 0..7
    #pragma unroll
    for (int i = 0; i < 8; ++i) {
        int row = rg + i * 8;
        tile[row * 65 + col] = s[(size_t)(h0 + row) * W_ + w0 + col];
    }
    __syncthreads();
    #pragma unroll
    for (int i = 0; i < 8; ++i) {
        int row = rg + i * 8;
        d[(size_t)(w0 + row) * H_ + h0 + col] = tile[col * 65 + row];
    }
}

// ---------------- K2: eH + v-transpose fused (512 threads) -------------------
__global__ void __launch_bounds__(512, 1) k2_eH_tr()
{
    extern __shared__ __align__(16) float sm[];
    const int id = blockIdx.x;
    if (id < 1024) {
        eH_body(id & 127, id >> 7, sm);
    } else {
        int r = id - 1024;
        int n = r >> 2, quad = r & 3;
        transpose_body(n, (quad & 1) * 64, (quad >> 1) * 64, sm);
    }
}

// ---------------- K3: eW + joint softmax (512 threads) -----------------------
__global__ void __launch_bounds__(512, 1) k3_eW_softmax()
{
    extern __shared__ __align__(16) float sm[];
    float* Qs = sm;               // [w 128][34]
    float* Ks = sm + 128 * 34;    // [v 128][34]
    float* Es = sm + 2 * 128 * 34;// [128][132]
    const int t = threadIdx.x;
    const int h = blockIdx.x & 127, b = blockIdx.x >> 7;
    {
        const float* qb = g_qc + ((size_t)b * HW_ + (size_t)h * W_) * CQ_;
        const float* kb = g_kc + ((size_t)b * HW_ + (size_t)h * W_) * CQ_;
        #pragma unroll
        for (int i = 0; i < 2; ++i) {
            int idx = t + i * 512;
            int r = idx >> 3, c4 = (idx & 7) * 4;
            st2x(&Qs[r * 34 + c4], *(const float4*)(qb + idx * 4));
            st2x(&Ks[r * 34 + c4], *(const float4*)(kb + idx * 4));
        }
    }
    __syncthreads();
    const int tx = t & 15, ty = t >> 4;
    u64 acc[4][8] = {};
    #pragma unroll 4
    for (int cp = 0; cp < 16; ++cp) {
        u64 a2[4], b2[8];
        #pragma unroll
        for (int i = 0; i < 4; ++i) a2[i] = *(const u64*)&Qs[(ty + 32 * i) * 34 + 2 * cp];
        #pragma unroll
        for (int j = 0; j < 8; ++j) b2[j] = *(const u64*)&Ks[(tx + 16 * j) * 34 + 2 * cp];
        #pragma unroll
        for (int i = 0; i < 4; ++i)
            #pragma unroll
            for (int j = 0; j < 8; ++j)
                fma2(acc[i][j], a2[i], b2[j]);
    }
    #pragma unroll
    for (int i = 0; i < 4; ++i)
        #pragma unroll
        for (int j = 0; j < 8; ++j)
            Es[(ty + 32 * i) * 132 + tx + 16 * j] = hadd2(acc[i][j]);
    __syncthreads();
    const int lane = t & 31, wid = t >> 5;  // 16 warps, 8 rows each
    #pragma unroll
    for (int grp = 0; grp < 2; ++grp) {
        float wv[4][4];
        int rr[4];
        #pragma unroll
        for (int s = 0; s < 4; ++s) {
            rr[s] = wid + 16 * (grp * 4 + s);
            float4 x = *(const float4*)&Es[rr[s] * 132 + lane * 4];
            wv[s][0] = x.x; wv[s][1] = x.y; wv[s][2] = x.z; wv[s][3] = x.w;
        }
        float thr[4];
        topk64x4(wv, thr);
        float hv[4][4];
        #pragma unroll
        for (int s = 0; s < 4; ++s) {
            #pragma unroll
            for (int j = 0; j < 4; ++j)
                wv[s][j] = (wv[s][j] >= thr[s]) ? wv[s][j] : NEGF;
            float4 x = *(const float4*)(g_att + (((size_t)b * H_ + h) * W_ + rr[s]) * 256 + lane * 4);
            hv[s][0] = x.x; hv[s][1] = x.y; hv[s][2] = x.z; hv[s][3] = x.w;
        }
        float m[4];
        #pragma unroll
        for (int s = 0; s < 4; ++s) {
            m[s] = NEGF;
            #pragma unroll
            for (int j = 0; j < 4; ++j) m[s] = fmaxf(m[s], fmaxf(wv[s][j], hv[s][j]));
        }
        #pragma unroll
        for (int off = 16; off; off >>= 1)
            #pragma unroll
            for (int s = 0; s < 4; ++s)
                m[s] = fmaxf(m[s], __shfl_xor_sync(0xffffffffu, m[s], off));
        float ph[4][4], pw[4][4], sum[4];
        #pragma unroll
        for (int s = 0; s < 4; ++s) {
            sum[s] = 0.f;
            #pragma unroll
            for (int j = 0; j < 4; ++j) {
                ph[s][j] = __expf(hv[s][j] - m[s]);
                pw[s][j] = __expf(wv[s][j] - m[s]);
                sum[s] += ph[s][j] + pw[s][j];
            }
        }
        #pragma unroll
        for (int off = 16; off; off >>= 1)
            #pragma unroll
            for (int s = 0; s < 4; ++s)
                sum[s] += __shfl_xor_sync(0xffffffffu, sum[s], off);
        #pragma unroll
        for (int s = 0; s < 4; ++s) {
            float inv = 1.0f / sum[s];
            float* arow = g_att + (((size_t)b * H_ + h) * W_ + rr[s]) * 256;
            *(float4*)(arow + lane * 4) =
                make_float4(ph[s][0]*inv, ph[s][1]*inv, ph[s][2]*inv, ph[s][3]*inv);
            *(float4*)(arow + 128 + lane * 4) =
                make_float4(pw[s][0]*inv, pw[s][1]*inv, pw[s][2]*inv, pw[s][3]*inv);
        }
    }
}

// ---------------- AV GEMM body (256 threads, 8x8 tile, c-tile 128) -----------
// HSIDE=true: outH (V from g_vt col w, att 0:128, write g_oht)
// HSIDE=false: outW (V from g_v row h, att 128:256, write g_ow)
template<bool HSIDE>
__device__ __forceinline__ void av_body(int c0, int p, int b, float* sm)
{
    float* Vs = sm;               // [c 128][130]
    float* As = sm + 128 * 130;   // [x 128][130]
    const int t = threadIdx.x;
    #pragma unroll
    for (int i = 0; i < 16; ++i) {
        int idx = t + i * 256;                 // 4096 float4s each
        int r = idx >> 5, c4 = (idx & 31) * 4;
        const float* vsrc = HSIDE
            ? g_vt + (((size_t)b * C_ + c0 + r) * W_ + p) * H_ + c4
            : g_v  + (((size_t)b * C_ + c0 + r) * H_ + p) * W_ + c4;
        st2x(&Vs[r * 130 + c4], *(const float4*)vsrc);
        const float* asrc = HSIDE
            ? g_att + (((size_t)b * H_ + r) * W_ + p) * 256 + c4
            : g_att + (((size_t)b * H_ + p) * W_ + r) * 256 + 128 + c4;
        st2x(&As[r * 130 + c4], *(const float4*)asrc);
    }
    __syncthreads();
    const int tx = t & 15, ty = t >> 4;
    u64 acc[8][8] = {};
    #pragma unroll 4
    for (int gp = 0; gp < 64; ++gp) {
        u64 a2[8], b2[8];
        #pragma unroll
        for (int i = 0; i < 8; ++i) a2[i] = *(const u64*)&Vs[(ty + 16 * i) * 130 + 2 * gp];
        #pragma unroll
        for (int j = 0; j < 8; ++j) b2[j] = *(const u64*)&As[(tx + 16 * j) * 130 + 2 * gp];
        #pragma unroll
        for (int i = 0; i < 8; ++i)
            #pragma unroll
            for (int j = 0; j < 8; ++j)
                fma2(acc[i][j], a2[i], b2[j]);
    }
    #pragma unroll
    for (int i = 0; i < 8; ++i) {
        const size_t rb = HSIDE
            ? (((size_t)b * C_ + c0 + ty + 16 * i) * W_ + p) * H_
            : (((size_t)b * C_ + c0 + ty + 16 * i) * H_ + p) * W_;
        float* dst = HSIDE ? g_oht : g_ow;
        #pragma unroll
        for (int j = 0; j < 8; ++j)
            dst[rb + tx + 16 * j] = hadd2(acc[i][j]);
    }
}

// ---------------- K4: outH + outW fused (256 threads) ------------------------
// blocks [0,2048): outH, [2048,4096): outW; decode: c0=(id&1)*128, p=(id>>1)&127, b=id>>8
__global__ void __launch_bounds__(256, 1) k4_out()
{
    extern __shared__ __align__(16) float sm[];
    int id = blockIdx.x;
    if (id < 2048) {
        av_body<true >((id & 1) * 128, (id >> 1) & 127, id >> 8, sm);
    } else {
        id -= 2048;
        av_body<false>((id & 1) * 128, (id >> 1) & 127, id >> 8, sm);
    }
}

// ---------------- K5: out = gamma*(outH^T + outW) + x1 -----------------------
__global__ void __launch_bounds__(256) k5_combine(
    const float* __restrict__ x1, const float* __restrict__ gamma,
    float* __restrict__ out)
{
    __shared__ float tile[32][33];
    const size_t n = blockIdx.z;
    const float* oht = g_oht + n * HW_;   // [w][h]
    const float* ow  = g_ow  + n * HW_;   // [h][w]
    const float* x   = x1    + n * HW_;
    float*       o   = out   + n * HW_;
    const int w0 = blockIdx.x * 32, h0 = blockIdx.y * 32;
    const int tx = threadIdx.x, ty = threadIdx.y;
    #pragma unroll
    for (int i = ty; i < 32; i += 8)
        tile[i][tx] = oht[(size_t)(w0 + i) * H_ + h0 + tx];
    __syncthreads();
    const float gm = gamma[0];
    #pragma unroll
    for (int i = ty; i < 32; i += 8) {
        size_t idx = (size_t)(h0 + i) * W_ + w0 + tx;
        o[idx] = gm * (tile[tx][i] + ow[idx]) + x[idx];
    }
}

// ---------------- launch ------------------------------------------------------
extern "C" void kernel_launch(void* const* d_in, const int* in_sizes, int n_in,
                              void* d_out, int out_size)
{
    (void)in_sizes; (void)n_in; (void)out_size;
    const float* x1    = (const float*)d_in[0];
    const float* x2    = (const float*)d_in[1];
    const float* Wq    = (const float*)d_in[2];
    const float* bq    = (const float*)d_in[3];
    const float* Wk    = (const float*)d_in[4];
    const float* bk    = (const float*)d_in[5];
    const float* Wv    = (const float*)d_in[6];
    const float* bv    = (const float*)d_in[7];
    const float* gamma = (const float*)d_in[8];
    float* out = (float*)d_out;

    const int SMEM_P = (2 * 128 * 34) * 4;              // 34816
    const int SMEM_A = (2 * 128 * 34 + 128 * 132) * 4;  // 102400
    const int SMEM_B = (2 * 128 * 130) * 4;             // 133120
    cudaFuncSetAttribute(k1_proj,       cudaFuncAttributeMaxDynamicSharedMemorySize, SMEM_P);
    cudaFuncSetAttribute(k2_eH_tr,      cudaFuncAttributeMaxDynamicSharedMemorySize, SMEM_A);
    cudaFuncSetAttribute(k3_eW_softmax, cudaFuncAttributeMaxDynamicSharedMemorySize, SMEM_A);
    cudaFuncSetAttribute(k4_out,        cudaFuncAttributeMaxDynamicSharedMemorySize, SMEM_B);

    k1_proj      <<<4096, 256, SMEM_P>>>(x1, x2, Wq, bq, Wk, bk, Wv, bv);
    k2_eH_tr     <<<1024 + 8192, 512, SMEM_A>>>();
    k3_eW_softmax<<<1024, 512, SMEM_A>>>();
    k4_out       <<<4096, 256, SMEM_B>>>();
    k5_combine   <<<dim3(4, 4, B_*C_), dim3(32, 8)>>>(x1, gamma, out);
}

// round 8
// speedup vs baseline: 1.7202x; 1.7202x over previous
#include <cuda_runtime.h>
#include <cstdint>

#define B_   8
#define C_   256
#define CQ_  32
#define H_   128
#define W_   128
#define HW_  (H_*W_)

typedef unsigned long long u64;

// ---------------- scratch ----------------------------------------------------
__device__ float g_qc [(size_t)B_*HW_*CQ_];   // [b, p(=h*W+w), c]
__device__ float g_kc [(size_t)B_*HW_*CQ_];   // [b, p, c]
__device__ float g_v  [(size_t)B_*C_*HW_];    // [b, c, h, w]
__device__ float g_vt [(size_t)B_*C_*HW_];    // [b, c, w, h]
__device__ float g_att[(size_t)B_*H_*W_*256]; // [b,h,w, 0:128=H-half, 128:256=W-half]
__device__ float g_oht[(size_t)B_*C_*HW_];    // outH transposed: [b,c,w,h]
__device__ float g_ow [(size_t)B_*C_*HW_];    // outW: [b,c,h,w]

#define NEGF (__int_as_float(0xff800000))

// ---------------- packed fp32x2 helpers --------------------------------------
__device__ __forceinline__ void fma2(u64& d, u64 a, u64 b) {
    asm("fma.rn.f32x2 %0, %1, %2, %0;" : "+l"(d) : "l"(a), "l"(b));
}
__device__ __forceinline__ float hadd2(u64 v) {
    float lo, hi;
    asm("mov.b64 {%0,%1}, %2;" : "=f"(lo), "=f"(hi) : "l"(v));
    return lo + hi;
}
__device__ __forceinline__ void st2x(float* p, float4 v) {   // 2x 8B stores
    *(float2*)p       = make_float2(v.x, v.y);
    *(float2*)(p + 2) = make_float2(v.z, v.w);
}

// ---------------- exact 64th-largest, 4 rows, packed counts + early exit -----
__device__ __forceinline__ void topk64x4(const float v[4][4], float thr[4])
{
    unsigned keys[4][4];
    #pragma unroll
    for (int r = 0; r < 4; ++r)
        #pragma unroll
        for (int j = 0; j < 4; ++j) {
            unsigned u = __float_as_uint(v[r][j]);
            keys[r][j] = (u & 0x80000000u) ? ~u : (u | 0x80000000u);
        }
    unsigned prefix[4] = {0, 0, 0, 0};
    unsigned need[4]   = {64, 64, 64, 64};
    unsigned cand[4]   = {128, 128, 128, 128};
    int      ebit[4]   = {0, 0, 0, 0};
    unsigned done = 0;

    for (int bit = 31; bit >= 0; --bit) {
        unsigned packed = 0;
        #pragma unroll
        for (int r = 0; r < 4; ++r) {
            if (!(done & (1u << r))) {            // warp-uniform branch
                unsigned want = (prefix[r] >> bit) | 1u;
                unsigned c = 0;
                #pragma unroll
                for (int j = 0; j < 4; ++j)
                    c += (unsigned)((keys[r][j] >> bit) == want);
                packed += c << (8 * r);
            }
        }
        packed = __reduce_add_sync(0xffffffffu, packed);
        #pragma unroll
        for (int r = 0; r < 4; ++r) {
            if (!(done & (1u << r))) {
                unsigned c = (packed >> (8 * r)) & 255u;
                if (c >= need[r]) { prefix[r] |= 1u << bit; cand[r] = c; }
                else              { need[r] -= c; cand[r] -= c; }
                if (cand[r] == need[r]) { done |= 1u << r; ebit[r] = bit; }
            }
        }
        if (done == 15u) break;
    }
    #pragma unroll
    for (int r = 0; r < 4; ++r) {
        unsigned key;
        if (done & (1u << r)) {                   // warp-uniform
            unsigned mn = 0xFFFFFFFFu;
            #pragma unroll
            for (int j = 0; j < 4; ++j) {
                bool match = (((keys[r][j] ^ prefix[r]) >> ebit[r]) == 0);
                unsigned cand_k = match ? keys[r][j] : 0xFFFFFFFFu;
                mn = cand_k < mn ? cand_k : mn;
            }
            key = __reduce_min_sync(0xffffffffu, mn);
        } else {
            key = prefix[r];                      // exact full-width prefix
        }
        unsigned u = (key & 0x80000000u) ? (key ^ 0x80000000u) : ~key;
        thr[r] = __uint_as_float(u);
    }
}

// ---------------- small projection body (q/k): 32o x 128p, 4x4 tile ----------
__device__ __forceinline__ void proj_qk_body(
    const float* __restrict__ X, const float* __restrict__ Wm,
    const float* __restrict__ bias, float* __restrict__ Y,
    int b, int p0, float* sm)
{
    float* Ws = sm;            // [32][34]
    float* Xs = sm + 32 * 34;  // [128 phys(p)][34]
    const int t  = threadIdx.x;
    const int tx = t & 31, ty = t >> 5;
    const float* Xb = X + (size_t)b * C_ * HW_ + p0;

    u64 acc[4][4] = {};
    for (int kc = 0; kc < C_; kc += 32) {
        #pragma unroll
        for (int i = 0; i < 4; ++i) {
            int idx = t + i * 256;
            int o = idx >> 5, c = idx & 31;
            Ws[o * 34 + c] = Wm[o * C_ + kc + c];
        }
        #pragma unroll
        for (int i = 0; i < 4; ++i) {            // Xs transposed fill, row-perm
            int idx = t + i * 256;
            int c = idx >> 5, p4 = idx & 31;
            float4 xv = *(const float4*)(Xb + (size_t)(kc + c) * HW_ + p4 * 4);
            Xs[(0 * 32 + p4) * 34 + c] = xv.x;
            Xs[(1 * 32 + p4) * 34 + c] = xv.y;
            Xs[(2 * 32 + p4) * 34 + c] = xv.z;
            Xs[(3 * 32 + p4) * 34 + c] = xv.w;
        }
        __syncthreads();
        #pragma unroll
        for (int cp = 0; cp < 16; ++cp) {
            u64 a2[4], b2[4];
            #pragma unroll
            for (int i = 0; i < 4; ++i)
                a2[i] = *(const u64*)&Ws[(ty * 4 + i) * 34 + 2 * cp];
            #pragma unroll
            for (int j = 0; j < 4; ++j)          // col p = tx*4+j -> phys j*32+tx
                b2[j] = *(const u64*)&Xs[(j * 32 + tx) * 34 + 2 * cp];
            #pragma unroll
            for (int i = 0; i < 4; ++i)
                #pragma unroll
                for (int j = 0; j < 4; ++j)
                    fma2(acc[i][j], a2[i], b2[j]);
        }
        __syncthreads();
    }
    #pragma unroll
    for (int j = 0; j < 4; ++j) {
        float4 r;
        r.x = hadd2(acc[0][j]) + bias[ty * 4 + 0];
        r.y = hadd2(acc[1][j]) + bias[ty * 4 + 1];
        r.z = hadd2(acc[2][j]) + bias[ty * 4 + 2];
        r.w = hadd2(acc[3][j]) + bias[ty * 4 + 3];
        *(float4*)(Y + ((size_t)b * HW_ + p0 + tx * 4 + j) * CQ_ + ty * 4) = r;
    }
}

// ---------------- v projection body: 128o x 128p, 8x8 tile -------------------
__device__ __forceinline__ void proj_v_body(
    const float* __restrict__ X, const float* __restrict__ Wm,
    const float* __restrict__ bias, float* __restrict__ Y,
    int b, int o0, int p0, float* sm)
{
    float* Ws = sm;             // [128 o][34]
    float* Xs = sm + 128 * 34;  // [128 p][34]
    const int t  = threadIdx.x;
    const int tx = t & 15, ty = t >> 4;
    const float* Xb = X + (size_t)b * C_ * HW_ + p0;

    u64 acc[8][8] = {};
    for (int kc = 0; kc < C_; kc += 32) {
        #pragma unroll
        for (int i = 0; i < 4; ++i) {            // Ws: straight copy
            int idx = t + i * 256;
            int o = idx >> 3, c4 = (idx & 7) * 4;
            st2x(&Ws[o * 34 + c4], *(const float4*)(Wm + (size_t)(o0 + o) * C_ + kc + c4));
        }
        #pragma unroll
        for (int i = 0; i < 4; ++i) {            // Xs: transposed fill
            int idx = t + i * 256;
            int c = idx >> 5, p4 = idx & 31;
            float4 xv = *(const float4*)(Xb + (size_t)(kc + c) * HW_ + p4 * 4);
            Xs[(p4 * 4 + 0) * 34 + c] = xv.x;
            Xs[(p4 * 4 + 1) * 34 + c] = xv.y;
            Xs[(p4 * 4 + 2) * 34 + c] = xv.z;
            Xs[(p4 * 4 + 3) * 34 + c] = xv.w;
        }
        __syncthreads();
        #pragma unroll
        for (int cp = 0; cp < 16; ++cp) {
            u64 a2[8], b2[8];
            #pragma unroll
            for (int i = 0; i < 8; ++i) a2[i] = *(const u64*)&Ws[(ty + 16 * i) * 34 + 2 * cp];
            #pragma unroll
            for (int j = 0; j < 8; ++j) b2[j] = *(const u64*)&Xs[(tx + 16 * j) * 34 + 2 * cp];
            #pragma unroll
            for (int i = 0; i < 8; ++i)
                #pragma unroll
                for (int j = 0; j < 8; ++j)
                    fma2(acc[i][j], a2[i], b2[j]);
        }
        __syncthreads();
    }
    #pragma unroll
    for (int i = 0; i < 8; ++i) {
        int o = o0 + ty + 16 * i;
        float bv = bias[o];
        float* dst = Y + ((size_t)b * C_ + o) * HW_ + p0;
        #pragma unroll
        for (int j = 0; j < 8; ++j)
            dst[tx + 16 * j] = hadd2(acc[i][j]) + bv;
    }
}

// ---------------- K1: all projections fused (256 threads, NO reg clamp) ------
// blocks [0,2048): projv(8x8), [2048,3072): projq, [3072,4096): projk
__global__ void __launch_bounds__(256) k1_proj(
    const float* __restrict__ x1, const float* __restrict__ x2,
    const float* __restrict__ Wq, const float* __restrict__ bq,
    const float* __restrict__ Wk, const float* __restrict__ bk,
    const float* __restrict__ Wv, const float* __restrict__ bv)
{
    extern __shared__ __align__(16) float sm[];
    const int id = blockIdx.x;
    if (id < 2048) {
        int b = id >> 8, oblk = (id >> 7) & 1, pblk = id & 127;
        proj_v_body(x2, Wv, bv, g_v, b, oblk * 128, pblk * 128, sm);
    } else if (id < 3072) {
        int r = id - 2048;
        proj_qk_body(x1, Wq, bq, g_qc, r >> 7, (r & 127) * 128, sm);
    } else {
        int r = id - 3072;
        proj_qk_body(x2, Wk, bk, g_kc, r >> 7, (r & 127) * 128, sm);
    }
}

// ---------------- eH body (512 threads) ---------------------------------------
__device__ __forceinline__ void eH_body(int w, int b, float* sm)
{
    float* Qs = sm;               // [h 128][34]
    float* Ks = sm + 128 * 34;    // [g 128][34]
    float* Es = sm + 2 * 128 * 34;// [128][132]
    const int t = threadIdx.x;
    {
        const float* qb = g_qc + ((size_t)b * HW_ + w) * CQ_;
        const float* kb = g_kc + ((size_t)b * HW_ + w) * CQ_;
        #pragma unroll
        for (int i = 0; i < 2; ++i) {
            int idx = t + i * 512;            // 1024 float4s
            int h = idx >> 3, c4 = (idx & 7) * 4;
            size_t off = (size_t)h * W_ * CQ_ + c4;
            st2x(&Qs[h * 34 + c4], *(const float4*)(qb + off));
            st2x(&Ks[h * 34 + c4], *(const float4*)(kb + off));
        }
    }
    __syncthreads();
    const int tx = t & 15, ty = t >> 4;
    u64 acc[4][8] = {};
    #pragma unroll 4
    for (int cp = 0; cp < 16; ++cp) {
        u64 a2[4], b2[8];
        #pragma unroll
        for (int i = 0; i < 4; ++i) a2[i] = *(const u64*)&Qs[(ty + 32 * i) * 34 + 2 * cp];
        #pragma unroll
        for (int j = 0; j < 8; ++j) b2[j] = *(const u64*)&Ks[(tx + 16 * j) * 34 + 2 * cp];
        #pragma unroll
        for (int i = 0; i < 4; ++i)
            #pragma unroll
            for (int j = 0; j < 8; ++j)
                fma2(acc[i][j], a2[i], b2[j]);
    }
    #pragma unroll
    for (int i = 0; i < 4; ++i) {
        int h = ty + 32 * i;
        #pragma unroll
        for (int j = 0; j < 8; ++j) {
            int g = tx + 16 * j;
            Es[h * 132 + g] = (h == g) ? NEGF : hadd2(acc[i][j]);
        }
    }
    __syncthreads();
    const int lane = t & 31, wid = t >> 5;  // 16 warps, 8 rows each
    #pragma unroll
    for (int grp = 0; grp < 2; ++grp) {
        float v[4][4];
        int rr[4];
        #pragma unroll
        for (int s = 0; s < 4; ++s) {
            rr[s] = wid + 16 * (grp * 4 + s);
            float4 x = *(const float4*)&Es[rr[s] * 132 + lane * 4];
            v[s][0] = x.x; v[s][1] = x.y; v[s][2] = x.z; v[s][3] = x.w;
        }
        float thr[4];
        topk64x4(v, thr);
        #pragma unroll
        for (int s = 0; s < 4; ++s) {
            float4 o;
            o.x = v[s][0] >= thr[s] ? v[s][0] : NEGF;
            o.y = v[s][1] >= thr[s] ? v[s][1] : NEGF;
            o.z = v[s][2] >= thr[s] ? v[s][2] : NEGF;
            o.w = v[s][3] >= thr[s] ? v[s][3] : NEGF;
            *(float4*)(g_att + (((size_t)b * H_ + rr[s]) * W_ + w) * 256 + lane * 4) = o;
        }
    }
}

// ---------------- transpose body: 64x64 tile, 512 threads --------------------
__device__ __forceinline__ void transpose_body(int n, int w0, int h0, float* sm)
{
    float* tile = sm;                       // [64][65]
    const float* s = g_v  + (size_t)n * HW_;
    float*       d = g_vt + (size_t)n * HW_;
    const int t = threadIdx.x;
    const int col = t & 63, rg = t >> 6;    // rg 0..7
    #pragma unroll
    for (int i = 0; i < 8; ++i) {
        int row = rg + i * 8;
        tile[row * 65 + col] = s[(size_t)(h0 + row) * W_ + w0 + col];
    }
    __syncthreads();
    #pragma unroll
    for (int i = 0; i < 8; ++i) {
        int row = rg + i * 8;
        d[(size_t)(w0 + row) * H_ + h0 + col] = tile[col * 65 + row];
    }
}

// ---------------- K2: eH + v-transpose fused (512 threads) -------------------
__global__ void __launch_bounds__(512, 1) k2_eH_tr()
{
    extern __shared__ __align__(16) float sm[];
    const int id = blockIdx.x;
    if (id < 1024) {
        eH_body(id & 127, id >> 7, sm);
    } else {
        int r = id - 1024;
        int n = r >> 2, quad = r & 3;
        transpose_body(n, (quad & 1) * 64, (quad >> 1) * 64, sm);
    }
}

// ---------------- K3: eW + joint softmax (512 threads) -----------------------
__global__ void __launch_bounds__(512, 1) k3_eW_softmax()
{
    extern __shared__ __align__(16) float sm[];
    float* Qs = sm;               // [w 128][34]
    float* Ks = sm + 128 * 34;    // [v 128][34]
    float* Es = sm + 2 * 128 * 34;// [128][132]
    const int t = threadIdx.x;
    const int h = blockIdx.x & 127, b = blockIdx.x >> 7;
    {
        const float* qb = g_qc + ((size_t)b * HW_ + (size_t)h * W_) * CQ_;
        const float* kb = g_kc + ((size_t)b * HW_ + (size_t)h * W_) * CQ_;
        #pragma unroll
        for (int i = 0; i < 2; ++i) {
            int idx = t + i * 512;
            int r = idx >> 3, c4 = (idx & 7) * 4;
            st2x(&Qs[r * 34 + c4], *(const float4*)(qb + idx * 4));
            st2x(&Ks[r * 34 + c4], *(const float4*)(kb + idx * 4));
        }
    }
    __syncthreads();
    const int tx = t & 15, ty = t >> 4;
    u64 acc[4][8] = {};
    #pragma unroll 4
    for (int cp = 0; cp < 16; ++cp) {
        u64 a2[4], b2[8];
        #pragma unroll
        for (int i = 0; i < 4; ++i) a2[i] = *(const u64*)&Qs[(ty + 32 * i) * 34 + 2 * cp];
        #pragma unroll
        for (int j = 0; j < 8; ++j) b2[j] = *(const u64*)&Ks[(tx + 16 * j) * 34 + 2 * cp];
        #pragma unroll
        for (int i = 0; i < 4; ++i)
            #pragma unroll
            for (int j = 0; j < 8; ++j)
                fma2(acc[i][j], a2[i], b2[j]);
    }
    #pragma unroll
    for (int i = 0; i < 4; ++i)
        #pragma unroll
        for (int j = 0; j < 8; ++j)
            Es[(ty + 32 * i) * 132 + tx + 16 * j] = hadd2(acc[i][j]);
    __syncthreads();
    const int lane = t & 31, wid = t >> 5;  // 16 warps, 8 rows each
    #pragma unroll
    for (int grp = 0; grp < 2; ++grp) {
        float wv[4][4];
        int rr[4];
        #pragma unroll
        for (int s = 0; s < 4; ++s) {
            rr[s] = wid + 16 * (grp * 4 + s);
            float4 x = *(const float4*)&Es[rr[s] * 132 + lane * 4];
            wv[s][0] = x.x; wv[s][1] = x.y; wv[s][2] = x.z; wv[s][3] = x.w;
        }
        float thr[4];
        topk64x4(wv, thr);
        float hv[4][4];
        #pragma unroll
        for (int s = 0; s < 4; ++s) {
            #pragma unroll
            for (int j = 0; j < 4; ++j)
                wv[s][j] = (wv[s][j] >= thr[s]) ? wv[s][j] : NEGF;
            float4 x = *(const float4*)(g_att + (((size_t)b * H_ + h) * W_ + rr[s]) * 256 + lane * 4);
            hv[s][0] = x.x; hv[s][1] = x.y; hv[s][2] = x.z; hv[s][3] = x.w;
        }
        float m[4];
        #pragma unroll
        for (int s = 0; s < 4; ++s) {
            m[s] = NEGF;
            #pragma unroll
            for (int j = 0; j < 4; ++j) m[s] = fmaxf(m[s], fmaxf(wv[s][j], hv[s][j]));
        }
        #pragma unroll
        for (int off = 16; off; off >>= 1)
            #pragma unroll
            for (int s = 0; s < 4; ++s)
                m[s] = fmaxf(m[s], __shfl_xor_sync(0xffffffffu, m[s], off));
        float ph[4][4], pw[4][4], sum[4];
        #pragma unroll
        for (int s = 0; s < 4; ++s) {
            sum[s] = 0.f;
            #pragma unroll
            for (int j = 0; j < 4; ++j) {
                ph[s][j] = __expf(hv[s][j] - m[s]);
                pw[s][j] = __expf(wv[s][j] - m[s]);
                sum[s] += ph[s][j] + pw[s][j];
            }
        }
        #pragma unroll
        for (int off = 16; off; off >>= 1)
            #pragma unroll
            for (int s = 0; s < 4; ++s)
                sum[s] += __shfl_xor_sync(0xffffffffu, sum[s], off);
        #pragma unroll
        for (int s = 0; s < 4; ++s) {
            float inv = 1.0f / sum[s];
            float* arow = g_att + (((size_t)b * H_ + h) * W_ + rr[s]) * 256;
            *(float4*)(arow + lane * 4) =
                make_float4(ph[s][0]*inv, ph[s][1]*inv, ph[s][2]*inv, ph[s][3]*inv);
            *(float4*)(arow + 128 + lane * 4) =
                make_float4(pw[s][0]*inv, pw[s][1]*inv, pw[s][2]*inv, pw[s][3]*inv);
        }
    }
}

// ---------------- AV GEMM body (256 threads, 8x8 tile, c-tile 128) -----------
// HSIDE=true: outH (V from g_vt col w, att 0:128, write g_oht)
// HSIDE=false: outW (V from g_v row h, att 128:256, write g_ow)
template<bool HSIDE>
__device__ __forceinline__ void av_body(int c0, int p, int b, float* sm)
{
    float* Vs = sm;               // [c 128][130]
    float* As = sm + 128 * 130;   // [x 128][130]
    const int t = threadIdx.x;
    #pragma unroll
    for (int i = 0; i < 16; ++i) {
        int idx = t + i * 256;                 // 4096 float4s each
        int r = idx >> 5, c4 = (idx & 31) * 4;
        const float* vsrc = HSIDE
            ? g_vt + (((size_t)b * C_ + c0 + r) * W_ + p) * H_ + c4
            : g_v  + (((size_t)b * C_ + c0 + r) * H_ + p) * W_ + c4;
        st2x(&Vs[r * 130 + c4], *(const float4*)vsrc);
        const float* asrc = HSIDE
            ? g_att + (((size_t)b * H_ + r) * W_ + p) * 256 + c4
            : g_att + (((size_t)b * H_ + p) * W_ + r) * 256 + 128 + c4;
        st2x(&As[r * 130 + c4], *(const float4*)asrc);
    }
    __syncthreads();
    const int tx = t & 15, ty = t >> 4;
    u64 acc[8][8] = {};
    #pragma unroll 4
    for (int gp = 0; gp < 64; ++gp) {
        u64 a2[8], b2[8];
        #pragma unroll
        for (int i = 0; i < 8; ++i) a2[i] = *(const u64*)&Vs[(ty + 16 * i) * 130 + 2 * gp];
        #pragma unroll
        for (int j = 0; j < 8; ++j) b2[j] = *(const u64*)&As[(tx + 16 * j) * 130 + 2 * gp];
        #pragma unroll
        for (int i = 0; i < 8; ++i)
            #pragma unroll
            for (int j = 0; j < 8; ++j)
                fma2(acc[i][j], a2[i], b2[j]);
    }
    #pragma unroll
    for (int i = 0; i < 8; ++i) {
        const size_t rb = HSIDE
            ? (((size_t)b * C_ + c0 + ty + 16 * i) * W_ + p) * H_
            : (((size_t)b * C_ + c0 + ty + 16 * i) * H_ + p) * W_;
        float* dst = HSIDE ? g_oht : g_ow;
        #pragma unroll
        for (int j = 0; j < 8; ++j)
            dst[rb + tx + 16 * j] = hadd2(acc[i][j]);
    }
}

// ---------------- K4: outH + outW fused (256 threads) ------------------------
// blocks [0,2048): outH, [2048,4096): outW; decode: c0=(id&1)*128, p=(id>>1)&127, b=id>>8
__global__ void __launch_bounds__(256, 1) k4_out()
{
    extern __shared__ __align__(16) float sm[];
    int id = blockIdx.x;
    if (id < 2048) {
        av_body<true >((id & 1) * 128, (id >> 1) & 127, id >> 8, sm);
    } else {
        id -= 2048;
        av_body<false>((id & 1) * 128, (id >> 1) & 127, id >> 8, sm);
    }
}

// ---------------- K5: out = gamma*(outH^T + outW) + x1 -----------------------
__global__ void __launch_bounds__(256) k5_combine(
    const float* __restrict__ x1, const float* __restrict__ gamma,
    float* __restrict__ out)
{
    __shared__ float tile[32][33];
    const size_t n = blockIdx.z;
    const float* oht = g_oht + n * HW_;   // [w][h]
    const float* ow  = g_ow  + n * HW_;   // [h][w]
    const float* x   = x1    + n * HW_;
    float*       o   = out   + n * HW_;
    const int w0 = blockIdx.x * 32, h0 = blockIdx.y * 32;
    const int tx = threadIdx.x, ty = threadIdx.y;
    #pragma unroll
    for (int i = ty; i < 32; i += 8)
        tile[i][tx] = oht[(size_t)(w0 + i) * H_ + h0 + tx];
    __syncthreads();
    const float gm = gamma[0];
    #pragma unroll
    for (int i = ty; i < 32; i += 8) {
        size_t idx = (size_t)(h0 + i) * W_ + w0 + tx;
        o[idx] = gm * (tile[tx][i] + ow[idx]) + x[idx];
    }
}

// ---------------- launch ------------------------------------------------------
extern "C" void kernel_launch(void* const* d_in, const int* in_sizes, int n_in,
                              void* d_out, int out_size)
{
    (void)in_sizes; (void)n_in; (void)out_size;
    const float* x1    = (const float*)d_in[0];
    const float* x2    = (const float*)d_in[1];
    const float* Wq    = (const float*)d_in[2];
    const float* bq    = (const float*)d_in[3];
    const float* Wk    = (const float*)d_in[4];
    const float* bk    = (const float*)d_in[5];
    const float* Wv    = (const float*)d_in[6];
    const float* bv    = (const float*)d_in[7];
    const float* gamma = (const float*)d_in[8];
    float* out = (float*)d_out;

    const int SMEM_P = (2 * 128 * 34) * 4;              // 34816
    const int SMEM_A = (2 * 128 * 34 + 128 * 132) * 4;  // 102400
    const int SMEM_B = (2 * 128 * 130) * 4;             // 133120
    cudaFuncSetAttribute(k1_proj,       cudaFuncAttributeMaxDynamicSharedMemorySize, SMEM_P);
    cudaFuncSetAttribute(k2_eH_tr,      cudaFuncAttributeMaxDynamicSharedMemorySize, SMEM_A);
    cudaFuncSetAttribute(k3_eW_softmax, cudaFuncAttributeMaxDynamicSharedMemorySize, SMEM_A);
    cudaFuncSetAttribute(k4_out,        cudaFuncAttributeMaxDynamicSharedMemorySize, SMEM_B);

    k1_proj      <<<4096, 256, SMEM_P>>>(x1, x2, Wq, bq, Wk, bk, Wv, bv);
    k2_eH_tr     <<<1024 + 8192, 512, SMEM_A>>>();
    k3_eW_softmax<<<1024, 512, SMEM_A>>>();
    k4_out       <<<4096, 256, SMEM_B>>>();
    k5_combine   <<<dim3(4, 4, B_*C_), dim3(32, 8)>>>(x1, gamma, out);
}

// round 10
// speedup vs baseline: 1.8711x; 1.0877x over previous
#include <cuda_runtime.h>
#include <cuda_bf16.h>
#include <cstdint>

#define B_   8
#define C_   256
#define CQ_  32
#define H_   128
#define W_   128
#define HW_  (H_*W_)

typedef unsigned long long u64;

// ---------------- scratch ----------------------------------------------------
__device__ float g_qc [(size_t)B_*HW_*CQ_];   // [b, p(=h*W+w), c]
__device__ float g_kc [(size_t)B_*HW_*CQ_];   // [b, p, c]
__device__ float g_v  [(size_t)B_*C_*HW_];    // [b, c, h, w]
__device__ float g_vt [(size_t)B_*C_*HW_];    // [b, c, w, h]
__device__ float g_att[(size_t)B_*H_*W_*256]; // [b,h,w, 0:128=H-half, 128:256=W-half]
__device__ float g_oht[(size_t)B_*C_*HW_];    // outH transposed: [b,c,w,h]
__device__ float g_ow [(size_t)B_*C_*HW_];    // outW: [b,c,h,w]

#define NEGF (__int_as_float(0xff800000))

// ---------------- packed fp32x2 helpers --------------------------------------
__device__ __forceinline__ void fma2(u64& d, u64 a, u64 b) {
    asm("fma.rn.f32x2 %0, %1, %2, %0;" : "+l"(d) : "l"(a), "l"(b));
}
__device__ __forceinline__ float hadd2(u64 v) {
    float lo, hi;
    asm("mov.b64 {%0,%1}, %2;" : "=f"(lo), "=f"(hi) : "l"(v));
    return lo + hi;
}
__device__ __forceinline__ void st2x(float* p, float4 v) {   // 2x 8B stores
    *(float2*)p       = make_float2(v.x, v.y);
    *(float2*)(p + 2) = make_float2(v.z, v.w);
}

// ---------------- bf16 split helpers ------------------------------------------
__device__ __forceinline__ u64 pack4bf(__nv_bfloat16 a, __nv_bfloat16 b,
                                        __nv_bfloat16 c, __nv_bfloat16 d) {
    unsigned lo = ((unsigned)__bfloat16_as_ushort(b) << 16) | __bfloat16_as_ushort(a);
    unsigned hi = ((unsigned)__bfloat16_as_ushort(d) << 16) | __bfloat16_as_ushort(c);
    return (u64)lo | ((u64)hi << 32);
}
__device__ __forceinline__ void split4(float4 v, u64& hi, u64& lo) {
    __nv_bfloat16 h0 = __float2bfloat16(v.x), h1 = __float2bfloat16(v.y);
    __nv_bfloat16 h2 = __float2bfloat16(v.z), h3 = __float2bfloat16(v.w);
    __nv_bfloat16 l0 = __float2bfloat16(v.x - __bfloat162float(h0));
    __nv_bfloat16 l1 = __float2bfloat16(v.y - __bfloat162float(h1));
    __nv_bfloat16 l2 = __float2bfloat16(v.z - __bfloat162float(h2));
    __nv_bfloat16 l3 = __float2bfloat16(v.w - __bfloat162float(h3));
    hi = pack4bf(h0, h1, h2, h3);
    lo = pack4bf(l0, l1, l2, l3);
}
// mma.sync m16n8k16 row.col bf16 -> f32 (compute_80 baseline, valid on compute_103)
__device__ __forceinline__ void mma16816(float c[4], const unsigned a[4], const unsigned b[2]) {
    asm volatile(
        "mma.sync.aligned.m16n8k16.row.col.f32.bf16.bf16.f32 "
        "{%0,%1,%2,%3}, {%4,%5,%6,%7}, {%8,%9}, {%0,%1,%2,%3};"
        : "+f"(c[0]), "+f"(c[1]), "+f"(c[2]), "+f"(c[3])
        : "r"(a[0]), "r"(a[1]), "r"(a[2]), "r"(a[3]), "r"(b[0]), "r"(b[1]));
}

// ---------------- exact 64th-largest, 4 rows, packed counts + early exit -----
__device__ __forceinline__ void topk64x4(const float v[4][4], float thr[4])
{
    unsigned keys[4][4];
    #pragma unroll
    for (int r = 0; r < 4; ++r)
        #pragma unroll
        for (int j = 0; j < 4; ++j) {
            unsigned u = __float_as_uint(v[r][j]);
            keys[r][j] = (u & 0x80000000u) ? ~u : (u | 0x80000000u);
        }
    unsigned prefix[4] = {0, 0, 0, 0};
    unsigned need[4]   = {64, 64, 64, 64};
    unsigned cand[4]   = {128, 128, 128, 128};
    int      ebit[4]   = {0, 0, 0, 0};
    unsigned done = 0;

    for (int bit = 31; bit >= 0; --bit) {
        unsigned packed = 0;
        #pragma unroll
        for (int r = 0; r < 4; ++r) {
            if (!(done & (1u << r))) {
                unsigned want = (prefix[r] >> bit) | 1u;
                unsigned c = 0;
                #pragma unroll
                for (int j = 0; j < 4; ++j)
                    c += (unsigned)((keys[r][j] >> bit) == want);
                packed += c << (8 * r);
            }
        }
        packed = __reduce_add_sync(0xffffffffu, packed);
        #pragma unroll
        for (int r = 0; r < 4; ++r) {
            if (!(done & (1u << r))) {
                unsigned c = (packed >> (8 * r)) & 255u;
                if (c >= need[r]) { prefix[r] |= 1u << bit; cand[r] = c; }
                else              { need[r] -= c; cand[r] -= c; }
                if (cand[r] == need[r]) { done |= 1u << r; ebit[r] = bit; }
            }
        }
        if (done == 15u) break;
    }
    #pragma unroll
    for (int r = 0; r < 4; ++r) {
        unsigned key;
        if (done & (1u << r)) {
            unsigned mn = 0xFFFFFFFFu;
            #pragma unroll
            for (int j = 0; j < 4; ++j) {
                bool match = (((keys[r][j] ^ prefix[r]) >> ebit[r]) == 0);
                unsigned cand_k = match ? keys[r][j] : 0xFFFFFFFFu;
                mn = cand_k < mn ? cand_k : mn;
            }
            key = __reduce_min_sync(0xffffffffu, mn);
        } else {
            key = prefix[r];
        }
        unsigned u = (key & 0x80000000u) ? (key ^ 0x80000000u) : ~key;
        thr[r] = __uint_as_float(u);
    }
}

// ---------------- small projection body (q/k): 32o x 128p, 4x4 tile ----------
__device__ __forceinline__ void proj_qk_body(
    const float* __restrict__ X, const float* __restrict__ Wm,
    const float* __restrict__ bias, float* __restrict__ Y,
    int b, int p0, float* sm)
{
    float* Ws = sm;            // [32][34]
    float* Xs = sm + 32 * 34;  // [128 phys(p)][34]
    const int t  = threadIdx.x;
    const int tx = t & 31, ty = t >> 5;
    const float* Xb = X + (size_t)b * C_ * HW_ + p0;

    u64 acc[4][4] = {};
    for (int kc = 0; kc < C_; kc += 32) {
        #pragma unroll
        for (int i = 0; i < 4; ++i) {
            int idx = t + i * 256;
            int o = idx >> 5, c = idx & 31;
            Ws[o * 34 + c] = Wm[o * C_ + kc + c];
        }
        #pragma unroll
        for (int i = 0; i < 4; ++i) {
            int idx = t + i * 256;
            int c = idx >> 5, p4 = idx & 31;
            float4 xv = *(const float4*)(Xb + (size_t)(kc + c) * HW_ + p4 * 4);
            Xs[(0 * 32 + p4) * 34 + c] = xv.x;
            Xs[(1 * 32 + p4) * 34 + c] = xv.y;
            Xs[(2 * 32 + p4) * 34 + c] = xv.z;
            Xs[(3 * 32 + p4) * 34 + c] = xv.w;
        }
        __syncthreads();
        #pragma unroll
        for (int cp = 0; cp < 16; ++cp) {
            u64 a2[4], b2[4];
            #pragma unroll
            for (int i = 0; i < 4; ++i)
                a2[i] = *(const u64*)&Ws[(ty * 4 + i) * 34 + 2 * cp];
            #pragma unroll
            for (int j = 0; j < 4; ++j)
                b2[j] = *(const u64*)&Xs[(j * 32 + tx) * 34 + 2 * cp];
            #pragma unroll
            for (int i = 0; i < 4; ++i)
                #pragma unroll
                for (int j = 0; j < 4; ++j)
                    fma2(acc[i][j], a2[i], b2[j]);
        }
        __syncthreads();
    }
    #pragma unroll
    for (int j = 0; j < 4; ++j) {
        float4 r;
        r.x = hadd2(acc[0][j]) + bias[ty * 4 + 0];
        r.y = hadd2(acc[1][j]) + bias[ty * 4 + 1];
        r.z = hadd2(acc[2][j]) + bias[ty * 4 + 2];
        r.w = hadd2(acc[3][j]) + bias[ty * 4 + 3];
        *(float4*)(Y + ((size_t)b * HW_ + p0 + tx * 4 + j) * CQ_ + ty * 4) = r;
    }
}

// ---------------- v projection body: 128o x 128p, 8x8 tile -------------------
__device__ __forceinline__ void proj_v_body(
    const float* __restrict__ X, const float* __restrict__ Wm,
    const float* __restrict__ bias, float* __restrict__ Y,
    int b, int o0, int p0, float* sm)
{
    float* Ws = sm;             // [128 o][34]
    float* Xs = sm + 128 * 34;  // [128 p][34]
    const int t  = threadIdx.x;
    const int tx = t & 15, ty = t >> 4;
    const float* Xb = X + (size_t)b * C_ * HW_ + p0;

    u64 acc[8][8] = {};
    for (int kc = 0; kc < C_; kc += 32) {
        #pragma unroll
        for (int i = 0; i < 4; ++i) {
            int idx = t + i * 256;
            int o = idx >> 3, c4 = (idx & 7) * 4;
            st2x(&Ws[o * 34 + c4], *(const float4*)(Wm + (size_t)(o0 + o) * C_ + kc + c4));
        }
        #pragma unroll
        for (int i = 0; i < 4; ++i) {
            int idx = t + i * 256;
            int c = idx >> 5, p4 = idx & 31;
            float4 xv = *(const float4*)(Xb + (size_t)(kc + c) * HW_ + p4 * 4);
            Xs[(p4 * 4 + 0) * 34 + c] = xv.x;
            Xs[(p4 * 4 + 1) * 34 + c] = xv.y;
            Xs[(p4 * 4 + 2) * 34 + c] = xv.z;
            Xs[(p4 * 4 + 3) * 34 + c] = xv.w;
        }
        __syncthreads();
        #pragma unroll
        for (int cp = 0; cp < 16; ++cp) {
            u64 a2[8], b2[8];
            #pragma unroll
            for (int i = 0; i < 8; ++i) a2[i] = *(const u64*)&Ws[(ty + 16 * i) * 34 + 2 * cp];
            #pragma unroll
            for (int j = 0; j < 8; ++j) b2[j] = *(const u64*)&Xs[(tx + 16 * j) * 34 + 2 * cp];
            #pragma unroll
            for (int i = 0; i < 8; ++i)
                #pragma unroll
                for (int j = 0; j < 8; ++j)
                    fma2(acc[i][j], a2[i], b2[j]);
        }
        __syncthreads();
    }
    #pragma unroll
    for (int i = 0; i < 8; ++i) {
        int o = o0 + ty + 16 * i;
        float bv = bias[o];
        float* dst = Y + ((size_t)b * C_ + o) * HW_ + p0;
        #pragma unroll
        for (int j = 0; j < 8; ++j)
            dst[tx + 16 * j] = hadd2(acc[i][j]) + bv;
    }
}

// ---------------- K1: all projections fused (256 threads) --------------------
__global__ void __launch_bounds__(256) k1_proj(
    const float* __restrict__ x1, const float* __restrict__ x2,
    const float* __restrict__ Wq, const float* __restrict__ bq,
    const float* __restrict__ Wk, const float* __restrict__ bk,
    const float* __restrict__ Wv, const float* __restrict__ bv)
{
    extern __shared__ __align__(16) float sm[];
    const int id = blockIdx.x;
    if (id < 2048) {
        int b = id >> 8, oblk = (id >> 7) & 1, pblk = id & 127;
        proj_v_body(x2, Wv, bv, g_v, b, oblk * 128, pblk * 128, sm);
    } else if (id < 3072) {
        int r = id - 2048;
        proj_qk_body(x1, Wq, bq, g_qc, r >> 7, (r & 127) * 128, sm);
    } else {
        int r = id - 3072;
        proj_qk_body(x2, Wk, bk, g_kc, r >> 7, (r & 127) * 128, sm);
    }
}

// ---------------- eH body (512 threads) ---------------------------------------
__device__ __forceinline__ void eH_body(int w, int b, float* sm)
{
    float* Qs = sm;               // [h 128][34]
    float* Ks = sm + 128 * 34;    // [g 128][34]
    float* Es = sm + 2 * 128 * 34;// [128][132]
    const int t = threadIdx.x;
    {
        const float* qb = g_qc + ((size_t)b * HW_ + w) * CQ_;
        const float* kb = g_kc + ((size_t)b * HW_ + w) * CQ_;
        #pragma unroll
        for (int i = 0; i < 2; ++i) {
            int idx = t + i * 512;
            int h = idx >> 3, c4 = (idx & 7) * 4;
            size_t off = (size_t)h * W_ * CQ_ + c4;
            st2x(&Qs[h * 34 + c4], *(const float4*)(qb + off));
            st2x(&Ks[h * 34 + c4], *(const float4*)(kb + off));
        }
    }
    __syncthreads();
    const int tx = t & 15, ty = t >> 4;
    u64 acc[4][8] = {};
    #pragma unroll 4
    for (int cp = 0; cp < 16; ++cp) {
        u64 a2[4], b2[8];
        #pragma unroll
        for (int i = 0; i < 4; ++i) a2[i] = *(const u64*)&Qs[(ty + 32 * i) * 34 + 2 * cp];
        #pragma unroll
        for (int j = 0; j < 8; ++j) b2[j] = *(const u64*)&Ks[(tx + 16 * j) * 34 + 2 * cp];
        #pragma unroll
        for (int i = 0; i < 4; ++i)
            #pragma unroll
            for (int j = 0; j < 8; ++j)
                fma2(acc[i][j], a2[i], b2[j]);
    }
    #pragma unroll
    for (int i = 0; i < 4; ++i) {
        int h = ty + 32 * i;
        #pragma unroll
        for (int j = 0; j < 8; ++j) {
            int g = tx + 16 * j;
            Es[h * 132 + g] = (h == g) ? NEGF : hadd2(acc[i][j]);
        }
    }
    __syncthreads();
    const int lane = t & 31, wid = t >> 5;
    #pragma unroll
    for (int grp = 0; grp < 2; ++grp) {
        float v[4][4];
        int rr[4];
        #pragma unroll
        for (int s = 0; s < 4; ++s) {
            rr[s] = wid + 16 * (grp * 4 + s);
            float4 x = *(const float4*)&Es[rr[s] * 132 + lane * 4];
            v[s][0] = x.x; v[s][1] = x.y; v[s][2] = x.z; v[s][3] = x.w;
        }
        float thr[4];
        topk64x4(v, thr);
        #pragma unroll
        for (int s = 0; s < 4; ++s) {
            float4 o;
            o.x = v[s][0] >= thr[s] ? v[s][0] : NEGF;
            o.y = v[s][1] >= thr[s] ? v[s][1] : NEGF;
            o.z = v[s][2] >= thr[s] ? v[s][2] : NEGF;
            o.w = v[s][3] >= thr[s] ? v[s][3] : NEGF;
            *(float4*)(g_att + (((size_t)b * H_ + rr[s]) * W_ + w) * 256 + lane * 4) = o;
        }
    }
}

// ---------------- transpose body: 64x64 tile, 512 threads --------------------
__device__ __forceinline__ void transpose_body(int n, int w0, int h0, float* sm)
{
    float* tile = sm;                       // [64][65]
    const float* s = g_v  + (size_t)n * HW_;
    float*       d = g_vt + (size_t)n * HW_;
    const int t = threadIdx.x;
    const int col = t & 63, rg = t >> 6;
    #pragma unroll
    for (int i = 0; i < 8; ++i) {
        int row = rg + i * 8;
        tile[row * 65 + col] = s[(size_t)(h0 + row) * W_ + w0 + col];
    }
    __syncthreads();
    #pragma unroll
    for (int i = 0; i < 8; ++i) {
        int row = rg + i * 8;
        d[(size_t)(w0 + row) * H_ + h0 + col] = tile[col * 65 + row];
    }
}

// ---------------- K2: eH + v-transpose fused (512 threads) -------------------
__global__ void __launch_bounds__(512, 1) k2_eH_tr()
{
    extern __shared__ __align__(16) float sm[];
    const int id = blockIdx.x;
    if (id < 1024) {
        eH_body(id & 127, id >> 7, sm);
    } else {
        int r = id - 1024;
        int n = r >> 2, quad = r & 3;
        transpose_body(n, (quad & 1) * 64, (quad >> 1) * 64, sm);
    }
}

// ---------------- K3: eW + joint softmax (512 threads) -----------------------
__global__ void __launch_bounds__(512, 1) k3_eW_softmax()
{
    extern __shared__ __align__(16) float sm[];
    float* Qs = sm;
    float* Ks = sm + 128 * 34;
    float* Es = sm + 2 * 128 * 34;
    const int t = threadIdx.x;
    const int h = blockIdx.x & 127, b = blockIdx.x >> 7;
    {
        const float* qb = g_qc + ((size_t)b * HW_ + (size_t)h * W_) * CQ_;
        const float* kb = g_kc + ((size_t)b * HW_ + (size_t)h * W_) * CQ_;
        #pragma unroll
        for (int i = 0; i < 2; ++i) {
            int idx = t + i * 512;
            int r = idx >> 3, c4 = (idx & 7) * 4;
            st2x(&Qs[r * 34 + c4], *(const float4*)(qb + idx * 4));
            st2x(&Ks[r * 34 + c4], *(const float4*)(kb + idx * 4));
        }
    }
    __syncthreads();
    const int tx = t & 15, ty = t >> 4;
    u64 acc[4][8] = {};
    #pragma unroll 4
    for (int cp = 0; cp < 16; ++cp) {
        u64 a2[4], b2[8];
        #pragma unroll
        for (int i = 0; i < 4; ++i) a2[i] = *(const u64*)&Qs[(ty + 32 * i) * 34 + 2 * cp];
        #pragma unroll
        for (int j = 0; j < 8; ++j) b2[j] = *(const u64*)&Ks[(tx + 16 * j) * 34 + 2 * cp];
        #pragma unroll
        for (int i = 0; i < 4; ++i)
            #pragma unroll
            for (int j = 0; j < 8; ++j)
                fma2(acc[i][j], a2[i], b2[j]);
    }
    #pragma unroll
    for (int i = 0; i < 4; ++i)
        #pragma unroll
        for (int j = 0; j < 8; ++j)
            Es[(ty + 32 * i) * 132 + tx + 16 * j] = hadd2(acc[i][j]);
    __syncthreads();
    const int lane = t & 31, wid = t >> 5;
    #pragma unroll
    for (int grp = 0; grp < 2; ++grp) {
        float wv[4][4];
        int rr[4];
        #pragma unroll
        for (int s = 0; s < 4; ++s) {
            rr[s] = wid + 16 * (grp * 4 + s);
            float4 x = *(const float4*)&Es[rr[s] * 132 + lane * 4];
            wv[s][0] = x.x; wv[s][1] = x.y; wv[s][2] = x.z; wv[s][3] = x.w;
        }
        float thr[4];
        topk64x4(wv, thr);
        float hv[4][4];
        #pragma unroll
        for (int s = 0; s < 4; ++s) {
            #pragma unroll
            for (int j = 0; j < 4; ++j)
                wv[s][j] = (wv[s][j] >= thr[s]) ? wv[s][j] : NEGF;
            float4 x = *(const float4*)(g_att + (((size_t)b * H_ + h) * W_ + rr[s]) * 256 + lane * 4);
            hv[s][0] = x.x; hv[s][1] = x.y; hv[s][2] = x.z; hv[s][3] = x.w;
        }
        float m[4];
        #pragma unroll
        for (int s = 0; s < 4; ++s) {
            m[s] = NEGF;
            #pragma unroll
            for (int j = 0; j < 4; ++j) m[s] = fmaxf(m[s], fmaxf(wv[s][j], hv[s][j]));
        }
        #pragma unroll
        for (int off = 16; off; off >>= 1)
            #pragma unroll
            for (int s = 0; s < 4; ++s)
                m[s] = fmaxf(m[s], __shfl_xor_sync(0xffffffffu, m[s], off));
        float ph[4][4], pw[4][4], sum[4];
        #pragma unroll
        for (int s = 0; s < 4; ++s) {
            sum[s] = 0.f;
            #pragma unroll
            for (int j = 0; j < 4; ++j) {
                ph[s][j] = __expf(hv[s][j] - m[s]);
                pw[s][j] = __expf(wv[s][j] - m[s]);
                sum[s] += ph[s][j] + pw[s][j];
            }
        }
        #pragma unroll
        for (int off = 16; off; off >>= 1)
            #pragma unroll
            for (int s = 0; s < 4; ++s)
                sum[s] += __shfl_xor_sync(0xffffffffu, sum[s], off);
        #pragma unroll
        for (int s = 0; s < 4; ++s) {
            float inv = 1.0f / sum[s];
            float* arow = g_att + (((size_t)b * H_ + h) * W_ + rr[s]) * 256;
            *(float4*)(arow + lane * 4) =
                make_float4(ph[s][0]*inv, ph[s][1]*inv, ph[s][2]*inv, ph[s][3]*inv);
            *(float4*)(arow + 128 + lane * 4) =
                make_float4(pw[s][0]*inv, pw[s][1]*inv, pw[s][2]*inv, pw[s][3]*inv);
        }
    }
}

// ---------------- K4: AV GEMM via mma.sync bf16-split ------------------------
// Per block: D[128 c][128 x] = sum_g V[c][g] * A[x][g], K=128.
// 3 passes: Vhi*Ahi + Vhi*Alo + Vlo*Ahi (lo*lo dropped ~2^-18).
#define KP    136                         // bf16 row pitch (conflict-free frags)
#define TILEB (128 * KP * 2)              // 34816 bytes per bf16 tile
#define OFF_VHI 0
#define OFF_VLO (TILEB)
#define OFF_AHI (2 * TILEB)
#define OFF_ALO (3 * TILEB)
#define SMEM_K4 (4 * TILEB)               // 139264 (stage reuses this)

template<bool HSIDE>
__device__ __forceinline__ void av_mma_body(int c0, int p, int b, char* sm)
{
    const int t = threadIdx.x, wid = t >> 5, lane = t & 31;
    const int gid = lane >> 2, tig = lane & 3;

    // ---- fill 4 bf16 tiles, linear [r][g] pitch KP ----
    const float* vbase = HSIDE ? g_vt + (((size_t)b * C_ + c0) * W_ + p) * H_
                               : g_v  + (((size_t)b * C_ + c0) * H_ + p) * W_;
    const float* abase = HSIDE ? g_att + ((size_t)b * HW_ + p) * 256
                               : g_att + (((size_t)b * H_ + p) * W_) * 256 + 128;
    const size_t astride = HSIDE ? (size_t)W_ * 256 : 256;

    #pragma unroll
    for (int i = 0; i < 16; ++i) {
        int idx = t + i * 256;
        int r = idx >> 5, g4 = (idx & 31) * 4;
        uint32_t so = (uint32_t)(r * KP + g4) * 2;
        u64 hi, lo;
        float4 v = *(const float4*)(vbase + (size_t)r * HW_ + g4);
        split4(v, hi, lo);
        *(u64*)(sm + OFF_VHI + so) = hi;
        *(u64*)(sm + OFF_VLO + so) = lo;
        float4 a = *(const float4*)(abase + (size_t)r * astride + g4);
        split4(a, hi, lo);
        *(u64*)(sm + OFF_AHI + so) = hi;
        *(u64*)(sm + OFF_ALO + so) = lo;
    }
    __syncthreads();

    // ---- warp tiles: wr in {0,1} (64 c), wc in {0..3} (32 x) ----
    const int wr = wid & 1, wc = wid >> 1;
    float acc[4][4][4] = {};
    #pragma unroll
    for (int ks = 0; ks < 8; ++ks) {
        const int k0 = ks * 16;
        unsigned aH[4][4], aL[4][4], bH[4][2], bL[4][2];
        #pragma unroll
        for (int i = 0; i < 4; ++i) {
            int rb = wr * 64 + i * 16 + gid;
            uint32_t o0 = (uint32_t)(rb * KP + k0 + tig * 2) * 2;
            uint32_t o1 = o0 + 8 * KP * 2;
            aH[i][0] = *(unsigned*)(sm + OFF_VHI + o0);
            aH[i][1] = *(unsigned*)(sm + OFF_VHI + o1);
            aH[i][2] = *(unsigned*)(sm + OFF_VHI + o0 + 16);
            aH[i][3] = *(unsigned*)(sm + OFF_VHI + o1 + 16);
            aL[i][0] = *(unsigned*)(sm + OFF_VLO + o0);
            aL[i][1] = *(unsigned*)(sm + OFF_VLO + o1);
            aL[i][2] = *(unsigned*)(sm + OFF_VLO + o0 + 16);
            aL[i][3] = *(unsigned*)(sm + OFF_VLO + o1 + 16);
        }
        #pragma unroll
        for (int j = 0; j < 4; ++j) {
            int xb = wc * 32 + j * 8 + gid;
            uint32_t o0 = (uint32_t)(xb * KP + k0 + tig * 2) * 2;
            bH[j][0] = *(unsigned*)(sm + OFF_AHI + o0);
            bH[j][1] = *(unsigned*)(sm + OFF_AHI + o0 + 16);
            bL[j][0] = *(unsigned*)(sm + OFF_ALO + o0);
            bL[j][1] = *(unsigned*)(sm + OFF_ALO + o0 + 16);
        }
        #pragma unroll
        for (int i = 0; i < 4; ++i)
            #pragma unroll
            for (int j = 0; j < 4; ++j) {
                mma16816(acc[i][j], aH[i], bH[j]);
                mma16816(acc[i][j], aH[i], bL[j]);
                mma16816(acc[i][j], aL[i], bH[j]);
            }
    }
    __syncthreads();   // tiles dead; reuse smem as fp32 stage [128][132]

    float* stage = (float*)sm;
    #pragma unroll
    for (int i = 0; i < 4; ++i)
        #pragma unroll
        for (int j = 0; j < 4; ++j) {
            int row = wr * 64 + i * 16 + gid;
            int col = wc * 32 + j * 8 + tig * 2;
            *(float2*)&stage[row * 132 + col]       = make_float2(acc[i][j][0], acc[i][j][1]);
            *(float2*)&stage[(row + 8) * 132 + col] = make_float2(acc[i][j][2], acc[i][j][3]);
        }
    __syncthreads();

    float* dstbase = HSIDE ? g_oht + (((size_t)b * C_ + c0) * W_ + p) * H_
                           : g_ow  + (((size_t)b * C_ + c0) * H_ + p) * W_;
    #pragma unroll
    for (int i = 0; i < 16; ++i) {
        int idx = t + i * 256;
        int r = idx >> 5, x4 = (idx & 31) * 4;
        float2 u2 = *(float2*)&stage[r * 132 + x4];
        float2 w2 = *(float2*)&stage[r * 132 + x4 + 2];
        *(float4*)(dstbase + (size_t)r * HW_ + x4) = make_float4(u2.x, u2.y, w2.x, w2.y);
    }
}

__global__ void __launch_bounds__(256) k4_out()
{
    extern __shared__ __align__(16) char smc[];
    int id = blockIdx.x;
    if (id < 2048) {
        av_mma_body<true >((id & 1) * 128, (id >> 1) & 127, id >> 8, smc);
    } else {
        id -= 2048;
        av_mma_body<false>((id & 1) * 128, (id >> 1) & 127, id >> 8, smc);
    }
}

// ---------------- K5: out = gamma*(outH^T + outW) + x1 -----------------------
__global__ void __launch_bounds__(256) k5_combine(
    const float* __restrict__ x1, const float* __restrict__ gamma,
    float* __restrict__ out)
{
    __shared__ float tile[32][33];
    const size_t n = blockIdx.z;
    const float* oht = g_oht + n * HW_;
    const float* ow  = g_ow  + n * HW_;
    const float* x   = x1    + n * HW_;
    float*       o   = out   + n * HW_;
    const int w0 = blockIdx.x * 32, h0 = blockIdx.y * 32;
    const int tx = threadIdx.x, ty = threadIdx.y;
    #pragma unroll
    for (int i = ty; i < 32; i += 8)
        tile[i][tx] = oht[(size_t)(w0 + i) * H_ + h0 + tx];
    __syncthreads();
    const float gm = gamma[0];
    #pragma unroll
    for (int i = ty; i < 32; i += 8) {
        size_t idx = (size_t)(h0 + i) * W_ + w0 + tx;
        o[idx] = gm * (tile[tx][i] + ow[idx]) + x[idx];
    }
}

// ---------------- launch ------------------------------------------------------
extern "C" void kernel_launch(void* const* d_in, const int* in_sizes, int n_in,
                              void* d_out, int out_size)
{
    (void)in_sizes; (void)n_in; (void)out_size;
    const float* x1    = (const float*)d_in[0];
    const float* x2    = (const float*)d_in[1];
    const float* Wq    = (const float*)d_in[2];
    const float* bq    = (const float*)d_in[3];
    const float* Wk    = (const float*)d_in[4];
    const float* bk    = (const float*)d_in[5];
    const float* Wv    = (const float*)d_in[6];
    const float* bv    = (const float*)d_in[7];
    const float* gamma = (const float*)d_in[8];
    float* out = (float*)d_out;

    const int SMEM_P = (2 * 128 * 34) * 4;              // 34816
    const int SMEM_A = (2 * 128 * 34 + 128 * 132) * 4;  // 102400
    cudaFuncSetAttribute(k1_proj,       cudaFuncAttributeMaxDynamicSharedMemorySize, SMEM_P);
    cudaFuncSetAttribute(k2_eH_tr,      cudaFuncAttributeMaxDynamicSharedMemorySize, SMEM_A);
    cudaFuncSetAttribute(k3_eW_softmax, cudaFuncAttributeMaxDynamicSharedMemorySize, SMEM_A);
    cudaFuncSetAttribute(k4_out,        cudaFuncAttributeMaxDynamicSharedMemorySize, SMEM_K4);

    k1_proj      <<<4096, 256, SMEM_P>>>(x1, x2, Wq, bq, Wk, bk, Wv, bv);
    k2_eH_tr     <<<1024 + 8192, 512, SMEM_A>>>();
    k3_eW_softmax<<<1024, 512, SMEM_A>>>();
    k4_out       <<<4096, 256, SMEM_K4>>>();
    k5_combine   <<<dim3(4, 4, B_*C_), dim3(32, 8)>>>(x1, gamma, out);
}

// round 12
// speedup vs baseline: 2.4237x; 1.2953x over previous
#include <cuda_runtime.h>
#include <cuda_bf16.h>
#include <cstdint>

#define B_   8
#define C_   256
#define CQ_  32
#define H_   128
#define W_   128
#define HW_  (H_*W_)

typedef unsigned long long u64;

// ---------------- scratch ----------------------------------------------------
__device__ float g_qc [(size_t)B_*HW_*CQ_];   // [b, p(=h*W+w), c]
__device__ float g_kc [(size_t)B_*HW_*CQ_];   // [b, p, c]
__device__ float g_v  [(size_t)B_*C_*HW_];    // [b, c, h, w]
__device__ float g_vt [(size_t)B_*C_*HW_];    // [b, c, w, h]
__device__ float g_att[(size_t)B_*H_*W_*256]; // [b,h,w, 0:128=H-half, 128:256=W-half]
__device__ float g_oht[(size_t)B_*C_*HW_];    // outH transposed: [b,c,w,h]
__device__ float g_ow [(size_t)B_*C_*HW_];    // outW: [b,c,h,w]

#define NEGF (__int_as_float(0xff800000))

// ---------------- packed fp32x2 helpers --------------------------------------
__device__ __forceinline__ void fma2(u64& d, u64 a, u64 b) {
    asm("fma.rn.f32x2 %0, %1, %2, %0;" : "+l"(d) : "l"(a), "l"(b));
}
__device__ __forceinline__ float hadd2(u64 v) {
    float lo, hi;
    asm("mov.b64 {%0,%1}, %2;" : "=f"(lo), "=f"(hi) : "l"(v));
    return lo + hi;
}
__device__ __forceinline__ void st2x(float* p, float4 v) {
    *(float2*)p       = make_float2(v.x, v.y);
    *(float2*)(p + 2) = make_float2(v.z, v.w);
}

// ---------------- bf16 split helpers ------------------------------------------
__device__ __forceinline__ u64 pack4bf(__nv_bfloat16 a, __nv_bfloat16 b,
                                        __nv_bfloat16 c, __nv_bfloat16 d) {
    unsigned lo = ((unsigned)__bfloat16_as_ushort(b) << 16) | __bfloat16_as_ushort(a);
    unsigned hi = ((unsigned)__bfloat16_as_ushort(d) << 16) | __bfloat16_as_ushort(c);
    return (u64)lo | ((u64)hi << 32);
}
__device__ __forceinline__ void split4(float4 v, u64& hi, u64& lo) {
    __nv_bfloat16 h0 = __float2bfloat16(v.x), h1 = __float2bfloat16(v.y);
    __nv_bfloat16 h2 = __float2bfloat16(v.z), h3 = __float2bfloat16(v.w);
    __nv_bfloat16 l0 = __float2bfloat16(v.x - __bfloat162float(h0));
    __nv_bfloat16 l1 = __float2bfloat16(v.y - __bfloat162float(h1));
    __nv_bfloat16 l2 = __float2bfloat16(v.z - __bfloat162float(h2));
    __nv_bfloat16 l3 = __float2bfloat16(v.w - __bfloat162float(h3));
    hi = pack4bf(h0, h1, h2, h3);
    lo = pack4bf(l0, l1, l2, l3);
}
// mma.sync m16n8k16 row.col bf16 -> f32 (compute_80 baseline PTX)
__device__ __forceinline__ void mma16816(float c[4], const unsigned a[4], const unsigned b[2]) {
    asm volatile(
        "mma.sync.aligned.m16n8k16.row.col.f32.bf16.bf16.f32 "
        "{%0,%1,%2,%3}, {%4,%5,%6,%7}, {%8,%9}, {%0,%1,%2,%3};"
        : "+f"(c[0]), "+f"(c[1]), "+f"(c[2]), "+f"(c[3])
        : "r"(a[0]), "r"(a[1]), "r"(a[2]), "r"(a[3]), "r"(b[0]), "r"(b[1]));
}

#define KP    136
#define TILEB (128 * KP * 2)              // 34816 bytes / bf16 tile
#define OFF_T0 0
#define OFF_T1 (TILEB)
#define OFF_T2 (2 * TILEB)
#define OFF_T3 (3 * TILEB)
#define SMEM_MMA (4 * TILEB)              // 139264

// load A frags (2 m16 tiles) at row base rb, kstep k0, from tiles hiOff/loOff
__device__ __forceinline__ void ldfragA(const char* sm, int hiOff, int loOff,
                                        int rb, int k0, int tig,
                                        unsigned aH[4], unsigned aL[4]) {
    uint32_t o0 = (uint32_t)(rb * KP + k0 + tig * 2) * 2;
    uint32_t o1 = o0 + 8 * KP * 2;
    aH[0] = *(const unsigned*)(sm + hiOff + o0);
    aH[1] = *(const unsigned*)(sm + hiOff + o1);
    aH[2] = *(const unsigned*)(sm + hiOff + o0 + 16);
    aH[3] = *(const unsigned*)(sm + hiOff + o1 + 16);
    aL[0] = *(const unsigned*)(sm + loOff + o0);
    aL[1] = *(const unsigned*)(sm + loOff + o1);
    aL[2] = *(const unsigned*)(sm + loOff + o0 + 16);
    aL[3] = *(const unsigned*)(sm + loOff + o1 + 16);
}
__device__ __forceinline__ void ldfragB(const char* sm, int hiOff, int loOff,
                                        int xb, int k0, int tig,
                                        unsigned bH[2], unsigned bL[2]) {
    uint32_t o0 = (uint32_t)(xb * KP + k0 + tig * 2) * 2;
    bH[0] = *(const unsigned*)(sm + hiOff + o0);
    bH[1] = *(const unsigned*)(sm + hiOff + o0 + 16);
    bL[0] = *(const unsigned*)(sm + loOff + o0);
    bL[1] = *(const unsigned*)(sm + loOff + o0 + 16);
}

// ---------------- exact 64th-largest, 4 rows, packed counts + early exit -----
__device__ __forceinline__ void topk64x4(const float v[4][4], float thr[4])
{
    unsigned keys[4][4];
    #pragma unroll
    for (int r = 0; r < 4; ++r)
        #pragma unroll
        for (int j = 0; j < 4; ++j) {
            unsigned u = __float_as_uint(v[r][j]);
            keys[r][j] = (u & 0x80000000u) ? ~u : (u | 0x80000000u);
        }
    unsigned prefix[4] = {0, 0, 0, 0};
    unsigned need[4]   = {64, 64, 64, 64};
    unsigned cand[4]   = {128, 128, 128, 128};
    int      ebit[4]   = {0, 0, 0, 0};
    unsigned done = 0;

    for (int bit = 31; bit >= 0; --bit) {
        unsigned packed = 0;
        #pragma unroll
        for (int r = 0; r < 4; ++r) {
            if (!(done & (1u << r))) {
                unsigned want = (prefix[r] >> bit) | 1u;
                unsigned c = 0;
                #pragma unroll
                for (int j = 0; j < 4; ++j)
                    c += (unsigned)((keys[r][j] >> bit) == want);
                packed += c << (8 * r);
            }
        }
        packed = __reduce_add_sync(0xffffffffu, packed);
        #pragma unroll
        for (int r = 0; r < 4; ++r) {
            if (!(done & (1u << r))) {
                unsigned c = (packed >> (8 * r)) & 255u;
                if (c >= need[r]) { prefix[r] |= 1u << bit; cand[r] = c; }
                else              { need[r] -= c; cand[r] -= c; }
                if (cand[r] == need[r]) { done |= 1u << r; ebit[r] = bit; }
            }
        }
        if (done == 15u) break;
    }
    #pragma unroll
    for (int r = 0; r < 4; ++r) {
        unsigned key;
        if (done & (1u << r)) {
            unsigned mn = 0xFFFFFFFFu;
            #pragma unroll
            for (int j = 0; j < 4; ++j) {
                bool match = (((keys[r][j] ^ prefix[r]) >> ebit[r]) == 0);
                unsigned cand_k = match ? keys[r][j] : 0xFFFFFFFFu;
                mn = cand_k < mn ? cand_k : mn;
            }
            key = __reduce_min_sync(0xffffffffu, mn);
        } else {
            key = prefix[r];
        }
        unsigned u = (key & 0x80000000u) ? (key ^ 0x80000000u) : ~key;
        thr[r] = __uint_as_float(u);
    }
}

// ---------------- K0: q/k projections (256 threads, 4x4 FFMA2) ---------------
__device__ __forceinline__ void proj_qk_body(
    const float* __restrict__ X, const float* __restrict__ Wm,
    const float* __restrict__ bias, float* __restrict__ Y,
    int b, int p0, float* sm)
{
    float* Ws = sm;            // [32][34]
    float* Xs = sm + 32 * 34;  // [128 phys(p)][34]
    const int t  = threadIdx.x;
    const int tx = t & 31, ty = t >> 5;
    const float* Xb = X + (size_t)b * C_ * HW_ + p0;

    u64 acc[4][4] = {};
    for (int kc = 0; kc < C_; kc += 32) {
        #pragma unroll
        for (int i = 0; i < 4; ++i) {
            int idx = t + i * 256;
            int o = idx >> 5, c = idx & 31;
            Ws[o * 34 + c] = Wm[o * C_ + kc + c];
        }
        #pragma unroll
        for (int i = 0; i < 4; ++i) {
            int idx = t + i * 256;
            int c = idx >> 5, p4 = idx & 31;
            float4 xv = *(const float4*)(Xb + (size_t)(kc + c) * HW_ + p4 * 4);
            Xs[(0 * 32 + p4) * 34 + c] = xv.x;
            Xs[(1 * 32 + p4) * 34 + c] = xv.y;
            Xs[(2 * 32 + p4) * 34 + c] = xv.z;
            Xs[(3 * 32 + p4) * 34 + c] = xv.w;
        }
        __syncthreads();
        #pragma unroll
        for (int cp = 0; cp < 16; ++cp) {
            u64 a2[4], b2[4];
            #pragma unroll
            for (int i = 0; i < 4; ++i)
                a2[i] = *(const u64*)&Ws[(ty * 4 + i) * 34 + 2 * cp];
            #pragma unroll
            for (int j = 0; j < 4; ++j)
                b2[j] = *(const u64*)&Xs[(j * 32 + tx) * 34 + 2 * cp];
            #pragma unroll
            for (int i = 0; i < 4; ++i)
                #pragma unroll
                for (int j = 0; j < 4; ++j)
                    fma2(acc[i][j], a2[i], b2[j]);
        }
        __syncthreads();
    }
    #pragma unroll
    for (int j = 0; j < 4; ++j) {
        float4 r;
        r.x = hadd2(acc[0][j]) + bias[ty * 4 + 0];
        r.y = hadd2(acc[1][j]) + bias[ty * 4 + 1];
        r.z = hadd2(acc[2][j]) + bias[ty * 4 + 2];
        r.w = hadd2(acc[3][j]) + bias[ty * 4 + 3];
        *(float4*)(Y + ((size_t)b * HW_ + p0 + tx * 4 + j) * CQ_ + ty * 4) = r;
    }
}

__global__ void __launch_bounds__(256) k0_qk(
    const float* __restrict__ x1, const float* __restrict__ x2,
    const float* __restrict__ Wq, const float* __restrict__ bq,
    const float* __restrict__ Wk, const float* __restrict__ bk)
{
    extern __shared__ __align__(16) float sm[];
    const int id = blockIdx.x;
    if (id < 1024) proj_qk_body(x1, Wq, bq, g_qc, id >> 7, (id & 127) * 128, sm);
    else { int r = id - 1024; proj_qk_body(x2, Wk, bk, g_kc, r >> 7, (r & 127) * 128, sm); }
}

// ---------------- K1: v projection via mma.sync (512 threads) ----------------
// Per block: Y[128 o][128 p] = W[128 o][256 c] * X[256 c][128 p] + bias
__global__ void __launch_bounds__(512) k1v_proj(
    const float* __restrict__ x2, const float* __restrict__ Wv,
    const float* __restrict__ bv)
{
    extern __shared__ __align__(16) char smc[];
    char* sm = smc;
    const int id = blockIdx.x;
    const int b = id >> 8, o0 = ((id >> 7) & 1) * 128, p0 = (id & 127) * 128;
    const int t = threadIdx.x, wid = t >> 5, lane = t & 31;
    const int gid = lane >> 2, tig = lane & 3;
    const int wr = wid & 3, wc = wid >> 2;   // 32 o x 32 p per warp

    float acc[2][4][4] = {};
    for (int kc = 0; kc < C_; kc += 128) {
        // W tiles: [o][c] straight, u64 stores
        #pragma unroll
        for (int i = 0; i < 8; ++i) {
            int idx = t + i * 512;                    // 4096 float4s
            int o = idx >> 5, c4 = (idx & 31) * 4;
            u64 hi, lo;
            split4(*(const float4*)(Wv + (size_t)(o0 + o) * C_ + kc + c4), hi, lo);
            *(u64*)(sm + OFF_T0 + (uint32_t)(o * KP + c4) * 2) = hi;
            *(u64*)(sm + OFF_T1 + (uint32_t)(o * KP + c4) * 2) = lo;
        }
        // X tiles: [p][c] transposed fill, 4 coalesced scalar loads pack along c
        const float* Xb = x2 + ((size_t)b * C_ + kc) * HW_ + p0;
        #pragma unroll
        for (int i = 0; i < 8; ++i) {
            int idx = t + i * 512;
            int c4 = (idx >> 7) * 4, p = idx & 127;
            float4 xv;
            xv.x = Xb[(size_t)(c4 + 0) * HW_ + p];
            xv.y = Xb[(size_t)(c4 + 1) * HW_ + p];
            xv.z = Xb[(size_t)(c4 + 2) * HW_ + p];
            xv.w = Xb[(size_t)(c4 + 3) * HW_ + p];
            u64 hi, lo;
            split4(xv, hi, lo);
            *(u64*)(sm + OFF_T2 + (uint32_t)(p * KP + c4) * 2) = hi;
            *(u64*)(sm + OFF_T3 + (uint32_t)(p * KP + c4) * 2) = lo;
        }
        __syncthreads();
        #pragma unroll
        for (int ks = 0; ks < 8; ++ks) {
            const int k0 = ks * 16;
            unsigned aH[2][4], aL[2][4], bH[4][2], bL[4][2];
            #pragma unroll
            for (int i = 0; i < 2; ++i)
                ldfragA(sm, OFF_T0, OFF_T1, wr * 32 + i * 16 + gid, k0, tig, aH[i], aL[i]);
            #pragma unroll
            for (int j = 0; j < 4; ++j)
                ldfragB(sm, OFF_T2, OFF_T3, wc * 32 + j * 8 + gid, k0, tig, bH[j], bL[j]);
            #pragma unroll
            for (int i = 0; i < 2; ++i)
                #pragma unroll
                for (int j = 0; j < 4; ++j) {
                    mma16816(acc[i][j], aH[i], bH[j]);
                    mma16816(acc[i][j], aH[i], bL[j]);
                    mma16816(acc[i][j], aL[i], bH[j]);
                }
        }
        __syncthreads();
    }
    // stage + bias + coalesced store
    float* stage = (float*)sm;     // [128 o][132 p]
    #pragma unroll
    for (int i = 0; i < 2; ++i)
        #pragma unroll
        for (int j = 0; j < 4; ++j) {
            int row = wr * 32 + i * 16 + gid;
            int col = wc * 32 + j * 8 + tig * 2;
            *(float2*)&stage[row * 132 + col]       = make_float2(acc[i][j][0], acc[i][j][1]);
            *(float2*)&stage[(row + 8) * 132 + col] = make_float2(acc[i][j][2], acc[i][j][3]);
        }
    __syncthreads();
    #pragma unroll
    for (int i = 0; i < 8; ++i) {
        int idx = t + i * 512;
        int o = idx >> 5, p4 = (idx & 31) * 4;
        float bvv = bv[o0 + o];
        float2 u2 = *(float2*)&stage[o * 132 + p4];
        float2 w2 = *(float2*)&stage[o * 132 + p4 + 2];
        *(float4*)(g_v + ((size_t)b * C_ + o0 + o) * HW_ + p0 + p4) =
            make_float4(u2.x + bvv, u2.y + bvv, w2.x + bvv, w2.y + bvv);
    }
}

// ---------------- eH body (512 threads) ---------------------------------------
__device__ __forceinline__ void eH_body(int w, int b, float* sm)
{
    float* Qs = sm;
    float* Ks = sm + 128 * 34;
    float* Es = sm + 2 * 128 * 34;
    const int t = threadIdx.x;
    {
        const float* qb = g_qc + ((size_t)b * HW_ + w) * CQ_;
        const float* kb = g_kc + ((size_t)b * HW_ + w) * CQ_;
        #pragma unroll
        for (int i = 0; i < 2; ++i) {
            int idx = t + i * 512;
            int h = idx >> 3, c4 = (idx & 7) * 4;
            size_t off = (size_t)h * W_ * CQ_ + c4;
            st2x(&Qs[h * 34 + c4], *(const float4*)(qb + off));
            st2x(&Ks[h * 34 + c4], *(const float4*)(kb + off));
        }
    }
    __syncthreads();
    const int tx = t & 15, ty = t >> 4;
    u64 acc[4][8] = {};
    #pragma unroll 4
    for (int cp = 0; cp < 16; ++cp) {
        u64 a2[4], b2[8];
        #pragma unroll
        for (int i = 0; i < 4; ++i) a2[i] = *(const u64*)&Qs[(ty + 32 * i) * 34 + 2 * cp];
        #pragma unroll
        for (int j = 0; j < 8; ++j) b2[j] = *(const u64*)&Ks[(tx + 16 * j) * 34 + 2 * cp];
        #pragma unroll
        for (int i = 0; i < 4; ++i)
            #pragma unroll
            for (int j = 0; j < 8; ++j)
                fma2(acc[i][j], a2[i], b2[j]);
    }
    #pragma unroll
    for (int i = 0; i < 4; ++i) {
        int h = ty + 32 * i;
        #pragma unroll
        for (int j = 0; j < 8; ++j) {
            int g = tx + 16 * j;
            Es[h * 132 + g] = (h == g) ? NEGF : hadd2(acc[i][j]);
        }
    }
    __syncthreads();
    const int lane = t & 31, wid = t >> 5;
    #pragma unroll
    for (int grp = 0; grp < 2; ++grp) {
        float v[4][4];
        int rr[4];
        #pragma unroll
        for (int s = 0; s < 4; ++s) {
            rr[s] = wid + 16 * (grp * 4 + s);
            float4 x = *(const float4*)&Es[rr[s] * 132 + lane * 4];
            v[s][0] = x.x; v[s][1] = x.y; v[s][2] = x.z; v[s][3] = x.w;
        }
        float thr[4];
        topk64x4(v, thr);
        #pragma unroll
        for (int s = 0; s < 4; ++s) {
            float4 o;
            o.x = v[s][0] >= thr[s] ? v[s][0] : NEGF;
            o.y = v[s][1] >= thr[s] ? v[s][1] : NEGF;
            o.z = v[s][2] >= thr[s] ? v[s][2] : NEGF;
            o.w = v[s][3] >= thr[s] ? v[s][3] : NEGF;
            *(float4*)(g_att + (((size_t)b * H_ + rr[s]) * W_ + w) * 256 + lane * 4) = o;
        }
    }
}

// ---------------- transpose body: 64x64 tile, 512 threads --------------------
__device__ __forceinline__ void transpose_body(int n, int w0, int h0, float* sm)
{
    float* tile = sm;
    const float* s = g_v  + (size_t)n * HW_;
    float*       d = g_vt + (size_t)n * HW_;
    const int t = threadIdx.x;
    const int col = t & 63, rg = t >> 6;
    #pragma unroll
    for (int i = 0; i < 8; ++i) {
        int row = rg + i * 8;
        tile[row * 65 + col] = s[(size_t)(h0 + row) * W_ + w0 + col];
    }
    __syncthreads();
    #pragma unroll
    for (int i = 0; i < 8; ++i) {
        int row = rg + i * 8;
        d[(size_t)(w0 + row) * H_ + h0 + col] = tile[col * 65 + row];
    }
}

// ---------------- K2: eH + v-transpose fused (512 threads) -------------------
__global__ void __launch_bounds__(512, 1) k2_eH_tr()
{
    extern __shared__ __align__(16) float sm[];
    const int id = blockIdx.x;
    if (id < 1024) {
        eH_body(id & 127, id >> 7, sm);
    } else {
        int r = id - 1024;
        int n = r >> 2, quad = r & 3;
        transpose_body(n, (quad & 1) * 64, (quad >> 1) * 64, sm);
    }
}

// ---------------- K3: eW + joint softmax (512 threads) -----------------------
__global__ void __launch_bounds__(512, 1) k3_eW_softmax()
{
    extern __shared__ __align__(16) float sm[];
    float* Qs = sm;
    float* Ks = sm + 128 * 34;
    float* Es = sm + 2 * 128 * 34;
    const int t = threadIdx.x;
    const int h = blockIdx.x & 127, b = blockIdx.x >> 7;
    {
        const float* qb = g_qc + ((size_t)b * HW_ + (size_t)h * W_) * CQ_;
        const float* kb = g_kc + ((size_t)b * HW_ + (size_t)h * W_) * CQ_;
        #pragma unroll
        for (int i = 0; i < 2; ++i) {
            int idx = t + i * 512;
            int r = idx >> 3, c4 = (idx & 7) * 4;
            st2x(&Qs[r * 34 + c4], *(const float4*)(qb + idx * 4));
            st2x(&Ks[r * 34 + c4], *(const float4*)(kb + idx * 4));
        }
    }
    __syncthreads();
    const int tx = t & 15, ty = t >> 4;
    u64 acc[4][8] = {};
    #pragma unroll 4
    for (int cp = 0; cp < 16; ++cp) {
        u64 a2[4], b2[8];
        #pragma unroll
        for (int i = 0; i < 4; ++i) a2[i] = *(const u64*)&Qs[(ty + 32 * i) * 34 + 2 * cp];
        #pragma unroll
        for (int j = 0; j < 8; ++j) b2[j] = *(const u64*)&Ks[(tx + 16 * j) * 34 + 2 * cp];
        #pragma unroll
        for (int i = 0; i < 4; ++i)
            #pragma unroll
            for (int j = 0; j < 8; ++j)
                fma2(acc[i][j], a2[i], b2[j]);
    }
    #pragma unroll
    for (int i = 0; i < 4; ++i)
        #pragma unroll
        for (int j = 0; j < 8; ++j)
            Es[(ty + 32 * i) * 132 + tx + 16 * j] = hadd2(acc[i][j]);
    __syncthreads();
    const int lane = t & 31, wid = t >> 5;
    #pragma unroll
    for (int grp = 0; grp < 2; ++grp) {
        float wv[4][4];
        int rr[4];
        #pragma unroll
        for (int s = 0; s < 4; ++s) {
            rr[s] = wid + 16 * (grp * 4 + s);
            float4 x = *(const float4*)&Es[rr[s] * 132 + lane * 4];
            wv[s][0] = x.x; wv[s][1] = x.y; wv[s][2] = x.z; wv[s][3] = x.w;
        }
        float thr[4];
        topk64x4(wv, thr);
        float hv[4][4];
        #pragma unroll
        for (int s = 0; s < 4; ++s) {
            #pragma unroll
            for (int j = 0; j < 4; ++j)
                wv[s][j] = (wv[s][j] >= thr[s]) ? wv[s][j] : NEGF;
            float4 x = *(const float4*)(g_att + (((size_t)b * H_ + h) * W_ + rr[s]) * 256 + lane * 4);
            hv[s][0] = x.x; hv[s][1] = x.y; hv[s][2] = x.z; hv[s][3] = x.w;
        }
        float m[4];
        #pragma unroll
        for (int s = 0; s < 4; ++s) {
            m[s] = NEGF;
            #pragma unroll
            for (int j = 0; j < 4; ++j) m[s] = fmaxf(m[s], fmaxf(wv[s][j], hv[s][j]));
        }
        #pragma unroll
        for (int off = 16; off; off >>= 1)
            #pragma unroll
            for (int s = 0; s < 4; ++s)
                m[s] = fmaxf(m[s], __shfl_xor_sync(0xffffffffu, m[s], off));
        float ph[4][4], pw[4][4], sum[4];
        #pragma unroll
        for (int s = 0; s < 4; ++s) {
            sum[s] = 0.f;
            #pragma unroll
            for (int j = 0; j < 4; ++j) {
                ph[s][j] = __expf(hv[s][j] - m[s]);
                pw[s][j] = __expf(wv[s][j] - m[s]);
                sum[s] += ph[s][j] + pw[s][j];
            }
        }
        #pragma unroll
        for (int off = 16; off; off >>= 1)
            #pragma unroll
            for (int s = 0; s < 4; ++s)
                sum[s] += __shfl_xor_sync(0xffffffffu, sum[s], off);
        #pragma unroll
        for (int s = 0; s < 4; ++s) {
            float inv = 1.0f / sum[s];
            float* arow = g_att + (((size_t)b * H_ + h) * W_ + rr[s]) * 256;
            *(float4*)(arow + lane * 4) =
                make_float4(ph[s][0]*inv, ph[s][1]*inv, ph[s][2]*inv, ph[s][3]*inv);
            *(float4*)(arow + 128 + lane * 4) =
                make_float4(pw[s][0]*inv, pw[s][1]*inv, pw[s][2]*inv, pw[s][3]*inv);
        }
    }
}

// ---------------- K4: AV GEMM via mma.sync (512 threads) ---------------------
template<bool HSIDE>
__device__ __forceinline__ void av_mma_body(int c0, int p, int b, char* sm)
{
    const int t = threadIdx.x, wid = t >> 5, lane = t & 31;
    const int gid = lane >> 2, tig = lane & 3;
    const int wr = wid & 3, wc = wid >> 2;   // 32 c x 32 x per warp

    const float* vbase = HSIDE ? g_vt + (((size_t)b * C_ + c0) * W_ + p) * H_
                               : g_v  + (((size_t)b * C_ + c0) * H_ + p) * W_;
    const float* abase = HSIDE ? g_att + ((size_t)b * HW_ + p) * 256
                               : g_att + (((size_t)b * H_ + p) * W_) * 256 + 128;
    const size_t astride = HSIDE ? (size_t)W_ * 256 : 256;

    #pragma unroll
    for (int i = 0; i < 8; ++i) {
        int idx = t + i * 512;
        int r = idx >> 5, g4 = (idx & 31) * 4;
        uint32_t so = (uint32_t)(r * KP + g4) * 2;
        u64 hi, lo;
        float4 v = *(const float4*)(vbase + (size_t)r * HW_ + g4);
        split4(v, hi, lo);
        *(u64*)(sm + OFF_T0 + so) = hi;
        *(u64*)(sm + OFF_T1 + so) = lo;
        float4 a = *(const float4*)(abase + (size_t)r * astride + g4);
        split4(a, hi, lo);
        *(u64*)(sm + OFF_T2 + so) = hi;
        *(u64*)(sm + OFF_T3 + so) = lo;
    }
    __syncthreads();

    float acc[2][4][4] = {};
    #pragma unroll
    for (int ks = 0; ks < 8; ++ks) {
        const int k0 = ks * 16;
        unsigned aH[2][4], aL[2][4], bH[4][2], bL[4][2];
        #pragma unroll
        for (int i = 0; i < 2; ++i)
            ldfragA(sm, OFF_T0, OFF_T1, wr * 32 + i * 16 + gid, k0, tig, aH[i], aL[i]);
        #pragma unroll
        for (int j = 0; j < 4; ++j)
            ldfragB(sm, OFF_T2, OFF_T3, wc * 32 + j * 8 + gid, k0, tig, bH[j], bL[j]);
        #pragma unroll
        for (int i = 0; i < 2; ++i)
            #pragma unroll
            for (int j = 0; j < 4; ++j) {
                mma16816(acc[i][j], aH[i], bH[j]);
                mma16816(acc[i][j], aH[i], bL[j]);
                mma16816(acc[i][j], aL[i], bH[j]);
            }
    }
    __syncthreads();

    float* stage = (float*)sm;   // [128][132]
    #pragma unroll
    for (int i = 0; i < 2; ++i)
        #pragma unroll
        for (int j = 0; j < 4; ++j) {
            int row = wr * 32 + i * 16 + gid;
            int col = wc * 32 + j * 8 + tig * 2;
            *(float2*)&stage[row * 132 + col]       = make_float2(acc[i][j][0], acc[i][j][1]);
            *(float2*)&stage[(row + 8) * 132 + col] = make_float2(acc[i][j][2], acc[i][j][3]);
        }
    __syncthreads();

    float* dstbase = HSIDE ? g_oht + (((size_t)b * C_ + c0) * W_ + p) * H_
                           : g_ow  + (((size_t)b * C_ + c0) * H_ + p) * W_;
    #pragma unroll
    for (int i = 0; i < 8; ++i) {
        int idx = t + i * 512;
        int r = idx >> 5, x4 = (idx & 31) * 4;
        float2 u2 = *(float2*)&stage[r * 132 + x4];
        float2 w2 = *(float2*)&stage[r * 132 + x4 + 2];
        *(float4*)(dstbase + (size_t)r * HW_ + x4) = make_float4(u2.x, u2.y, w2.x, w2.y);
    }
}

__global__ void __launch_bounds__(512) k4_out()
{
    extern __shared__ __align__(16) char smc[];
    int id = blockIdx.x;
    if (id < 2048) {
        av_mma_body<true >((id & 1) * 128, (id >> 1) & 127, id >> 8, smc);
    } else {
        id -= 2048;
        av_mma_body<false>((id & 1) * 128, (id >> 1) & 127, id >> 8, smc);
    }
}

// ---------------- K5: out = gamma*(outH^T + outW) + x1 -----------------------
__global__ void __launch_bounds__(256) k5_combine(
    const float* __restrict__ x1, const float* __restrict__ gamma,
    float* __restrict__ out)
{
    __shared__ float tile[32][33];
    const size_t n = blockIdx.z;
    const float* oht = g_oht + n * HW_;
    const float* ow  = g_ow  + n * HW_;
    const float* x   = x1    + n * HW_;
    float*       o   = out   + n * HW_;
    const int w0 = blockIdx.x * 32, h0 = blockIdx.y * 32;
    const int tx = threadIdx.x, ty = threadIdx.y;
    #pragma unroll
    for (int i = ty; i < 32; i += 8)
        tile[i][tx] = oht[(size_t)(w0 + i) * H_ + h0 + tx];
    __syncthreads();
    const float gm = gamma[0];
    #pragma unroll
    for (int i = ty; i < 32; i += 8) {
        size_t idx = (size_t)(h0 + i) * W_ + w0 + tx;
        o[idx] = gm * (tile[tx][i] + ow[idx]) + x[idx];
    }
}

// ---------------- launch ------------------------------------------------------
extern "C" void kernel_launch(void* const* d_in, const int* in_sizes, int n_in,
                              void* d_out, int out_size)
{
    (void)in_sizes; (void)n_in; (void)out_size;
    const float* x1    = (const float*)d_in[0];
    const float* x2    = (const float*)d_in[1];
    const float* Wq    = (const float*)d_in[2];
    const float* bq    = (const float*)d_in[3];
    const float* Wk    = (const float*)d_in[4];
    const float* bk    = (const float*)d_in[5];
    const float* Wv    = (const float*)d_in[6];
    const float* bv    = (const float*)d_in[7];
    const float* gamma = (const float*)d_in[8];
    float* out = (float*)d_out;

    const int SMEM_P = (32 * 34 + 128 * 34) * 4;        // 21760
    const int SMEM_A = (2 * 128 * 34 + 128 * 132) * 4;  // 102400
    cudaFuncSetAttribute(k0_qk,         cudaFuncAttributeMaxDynamicSharedMemorySize, SMEM_P);
    cudaFuncSetAttribute(k1v_proj,      cudaFuncAttributeMaxDynamicSharedMemorySize, SMEM_MMA);
    cudaFuncSetAttribute(k2_eH_tr,      cudaFuncAttributeMaxDynamicSharedMemorySize, SMEM_A);
    cudaFuncSetAttribute(k3_eW_softmax, cudaFuncAttributeMaxDynamicSharedMemorySize, SMEM_A);
    cudaFuncSetAttribute(k4_out,        cudaFuncAttributeMaxDynamicSharedMemorySize, SMEM_MMA);

    k0_qk        <<<2048, 256, SMEM_P>>>(x1, x2, Wq, bq, Wk, bk);
    k1v_proj     <<<2048, 512, SMEM_MMA>>>(x2, Wv, bv);
    k2_eH_tr     <<<1024 + 8192, 512, SMEM_A>>>();
    k3_eW_softmax<<<1024, 512, SMEM_A>>>();
    k4_out       <<<4096, 512, SMEM_MMA>>>();
    k5_combine   <<<dim3(4, 4, B_*C_), dim3(32, 8)>>>(x1, gamma, out);
}